// round 1
// baseline (speedup 1.0000x reference)
#include <cuda_runtime.h>
#include <cstdint>

// Problem constants
#define BATCH 8
#define NSEQ  4096
#define CH    256
#define HEADS 8
#define HD    32
#define TOK   (BATCH * NSEQ)          // 32768 tokens
#define ELEMS (TOK * CH)              // 8,388,608

// ---------------- scratch (device globals; no allocation allowed) ----------
__device__ float  g_QL [ELEMS];       // token-major [b,n,c]
__device__ float  g_KL [ELEMS];
__device__ float  g_VL [ELEMS];
__device__ float  g_QLt[ELEMS];       // channel-major [b,c,n]
__device__ float  g_KLt[ELEMS];
__device__ float2 g_Q1 [ELEMS];       // seq-spectra, layout [(b*256+c), f]
__device__ float2 g_K1 [ELEMS];
__device__ float2 g_P1 [ELEMS];
__device__ float  g_ATTt[ELEMS];      // [b,c,n]
__device__ float  g_ATT [ELEMS];      // [b,n,c]
__device__ float2 g_tw [2048];        // exp(-2*pi*i*j/4096), j=0..2047

// ---------------- twiddle init (recomputed every call; deterministic) ------
__global__ void init_tw_kernel() {
    int j = blockIdx.x * blockDim.x + threadIdx.x;
    if (j < 2048) {
        double a = -2.0 * 3.14159265358979323846 * (double)j / 4096.0;
        g_tw[j] = make_float2((float)cos(a), (float)sin(a));
    }
}

// ---------------- projection GEMM: Out = X @ W^T + b -----------------------
// M=32768, N=256, K=256.  BM=128, BN=64, BK=16, 256 threads, 8x4 per thread.
__global__ void proj_gemm_kernel(const float* __restrict__ X,
                                 const float* __restrict__ W,
                                 const float* __restrict__ bias,
                                 int which) {
    float* Out = (which == 0) ? g_QL : (which == 1) ? g_KL : g_VL;
    __shared__ float Xs[16][128];
    __shared__ float Ws[16][64];
    int tid = threadIdx.x;
    int bm = blockIdx.x * 128;
    int bn = blockIdx.y * 64;
    int tx = tid & 15;   // n dir (16 * 4 = 64)
    int ty = tid >> 4;   // m dir (16 * 8 = 128)
    float acc[8][4];
#pragma unroll
    for (int i = 0; i < 8; i++)
#pragma unroll
        for (int j = 0; j < 4; j++) acc[i][j] = 0.f;

    for (int k0 = 0; k0 < 256; k0 += 16) {
#pragma unroll
        for (int i = 0; i < 2; i++) {
            int v = tid + i * 256;           // 0..511
            int row = v >> 2;                // 0..127
            int c4  = (v & 3) * 4;           // 0,4,8,12
            float4 x = *(const float4*)(X + (size_t)(bm + row) * 256 + k0 + c4);
            Xs[c4 + 0][row] = x.x; Xs[c4 + 1][row] = x.y;
            Xs[c4 + 2][row] = x.z; Xs[c4 + 3][row] = x.w;
        }
        {
            int row = tid >> 2;              // 0..63
            int c4  = (tid & 3) * 4;
            float4 w = *(const float4*)(W + (size_t)(bn + row) * 256 + k0 + c4);
            Ws[c4 + 0][row] = w.x; Ws[c4 + 1][row] = w.y;
            Ws[c4 + 2][row] = w.z; Ws[c4 + 3][row] = w.w;
        }
        __syncthreads();
#pragma unroll
        for (int k = 0; k < 16; k++) {
            float a[8], bb[4];
#pragma unroll
            for (int i = 0; i < 8; i++) a[i] = Xs[k][ty * 8 + i];
#pragma unroll
            for (int j = 0; j < 4; j++) bb[j] = Ws[k][tx * 4 + j];
#pragma unroll
            for (int i = 0; i < 8; i++)
#pragma unroll
                for (int j = 0; j < 4; j++) acc[i][j] = fmaf(a[i], bb[j], acc[i][j]);
        }
        __syncthreads();
    }
    float4 b4 = *(const float4*)(bias + bn + tx * 4);
#pragma unroll
    for (int i = 0; i < 8; i++) {
        int m = bm + ty * 8 + i;
        float4 o;
        o.x = acc[i][0] + b4.x; o.y = acc[i][1] + b4.y;
        o.z = acc[i][2] + b4.z; o.w = acc[i][3] + b4.w;
        *(float4*)(Out + (size_t)m * 256 + bn + tx * 4) = o;
    }
}

// ---------------- batched 4096x256 transpose -------------------------------
// mode 0: QL->QLt, KL->KLt (z = b*2 + tensor, 16 z-slices)
// mode 1: ATTt->ATT        (z = b, 8 z-slices)
__global__ void transpose_kernel(int mode) {
    __shared__ float tile[32][33];
    int n0 = blockIdx.x * 32;
    int c0 = blockIdx.y * 32;
    int tx = threadIdx.x, ty = threadIdx.y;
    if (mode == 0) {
        int b = blockIdx.z >> 1;
        const float* src = (blockIdx.z & 1) ? g_KL : g_QL;
        float*       dst = (blockIdx.z & 1) ? g_KLt : g_QLt;
#pragma unroll
        for (int j = 0; j < 32; j += 8)
            tile[ty + j][tx] = src[((size_t)b * NSEQ + n0 + ty + j) * 256 + c0 + tx];
        __syncthreads();
#pragma unroll
        for (int j = 0; j < 32; j += 8)
            dst[((size_t)b * 256 + c0 + ty + j) * NSEQ + n0 + tx] = tile[tx][ty + j];
    } else {
        int b = blockIdx.z;
#pragma unroll
        for (int j = 0; j < 32; j += 8)
            tile[ty + j][tx] = g_ATTt[((size_t)b * 256 + c0 + ty + j) * NSEQ + n0 + tx];
        __syncthreads();
#pragma unroll
        for (int j = 0; j < 32; j += 8)
            g_ATT[((size_t)b * NSEQ + n0 + ty + j) * 256 + c0 + tx] = tile[tx][ty + j];
    }
}

// ---------------- shared-memory radix-2 FFT (4096 pt) ----------------------
template <int INV>
__device__ __forceinline__ void fft4096(float2* z) {
    for (int half = 1; half < NSEQ; half <<= 1) {
        int step = 2048 / half;
        for (int t = threadIdx.x; t < 2048; t += blockDim.x) {
            int j = t & (half - 1);
            int i = ((t - j) << 1) + j;
            float2 w = g_tw[j * step];
            if (INV) w.y = -w.y;
            float2 u = z[i];
            float2 v = z[i + half];
            float2 vw = make_float2(v.x * w.x - v.y * w.y, v.x * w.y + v.y * w.x);
            z[i]        = make_float2(u.x + vw.x, u.y + vw.y);
            z[i + half] = make_float2(u.x - vw.x, u.y - vw.y);
        }
        __syncthreads();
    }
}

// ---------------- forward seq FFT, packed z = ql + i*kl --------------------
// one block per (b, c) column; extracts Qhat, Khat via hermitian split.
__global__ void fft_fwd_kernel() {
    __shared__ float2 z[NSEQ];
    int blk = blockIdx.x;             // 0..2047
    int b = blk >> 8;
    int c = blk & 255;
    size_t col = (size_t)(b * 256 + c) * NSEQ;
    for (int n = threadIdx.x; n < NSEQ; n += blockDim.x) {
        int r = __brev((unsigned)n) >> 20;
        z[r] = make_float2(g_QLt[col + n], g_KLt[col + n]);
    }
    __syncthreads();
    fft4096<0>(z);
    for (int f = threadIdx.x; f < NSEQ; f += blockDim.x) {
        int g = (NSEQ - f) & (NSEQ - 1);
        float2 zf = z[f], zg = z[g];
        g_Q1[col + f] = make_float2(0.5f * (zf.x + zg.x), 0.5f * (zf.y - zg.y));
        g_K1[col + f] = make_float2(0.5f * (zf.y + zg.y), 0.5f * (zg.x - zf.x));
    }
}

// ---------------- per-frequency circular conv over head_dim (32) -----------
// P[f,d] = sum_e Qhat[f,e] * Khat[f,(d-e)%32]   (complex)
// Block: 512 threads, tile = 64 freqs x all 32 d for one (b,h).
__global__ void dconv_kernel() {
    __shared__ float Qre[32][65], Qim[32][65], Kre[32][65], Kim[32][65];
    int f0 = blockIdx.x * 64;
    int bh = blockIdx.y;              // 0..63
    size_t base = (size_t)bh * 32 * NSEQ;
    int tid = threadIdx.x;
#pragma unroll
    for (int i = 0; i < 2; i++) {
        int vv = tid + i * 512;       // 0..1023
        int d  = vv >> 5;             // 0..31
        int j  = vv & 31;             // float4 index -> 2 freqs
        const float4* sq = (const float4*)(g_Q1 + base + (size_t)d * NSEQ + f0);
        const float4* sk = (const float4*)(g_K1 + base + (size_t)d * NSEQ + f0);
        float4 x = sq[j];
        Qre[d][2 * j] = x.x; Qim[d][2 * j] = x.y;
        Qre[d][2 * j + 1] = x.z; Qim[d][2 * j + 1] = x.w;
        float4 y = sk[j];
        Kre[d][2 * j] = y.x; Kim[d][2 * j] = y.y;
        Kre[d][2 * j + 1] = y.z; Kim[d][2 * j + 1] = y.w;
    }
    __syncthreads();
    int w = tid >> 5, lane = tid & 31;
#pragma unroll
    for (int rep = 0; rep < 4; rep++) {
        int f = w + rep * 16;
        float qr = Qre[lane][f], qi = Qim[lane][f];
        float kr = Kre[lane][f], ki = Kim[lane][f];
        float ar = 0.f, ai = 0.f;
#pragma unroll
        for (int e = 0; e < 32; e++) {
            float qer = __shfl_sync(0xffffffffu, qr, e);
            float qei = __shfl_sync(0xffffffffu, qi, e);
            int srcl = (lane - e) & 31;
            float ker = __shfl_sync(0xffffffffu, kr, srcl);
            float kei = __shfl_sync(0xffffffffu, ki, srcl);
            ar = fmaf(qer, ker, fmaf(-qei, kei, ar));
            ai = fmaf(qer, kei, fmaf(qei, ker, ai));
        }
        Qre[lane][f] = ar;  // safe: each column owned by exactly one warp
        Qim[lane][f] = ai;
    }
    __syncthreads();
#pragma unroll
    for (int i = 0; i < 2; i++) {
        int vv = tid + i * 512;
        int d  = vv >> 5;
        int j  = vv & 31;
        float4* dst = (float4*)(g_P1 + base + (size_t)d * NSEQ + f0);
        float4 x;
        x.x = Qre[d][2 * j];     x.y = Qim[d][2 * j];
        x.z = Qre[d][2 * j + 1]; x.w = Qim[d][2 * j + 1];
        dst[j] = x;
    }
}

// ---------------- inverse seq FFT, packed pair of d-columns ----------------
// z = P[:,d0] + i*P[:,d0+1]; both ifft outputs are real (hermitian spectra).
__global__ void fft_inv_kernel() {
    __shared__ float2 z[NSEQ];
    int blk = blockIdx.x;             // 0..1023
    int bh = blk >> 4;                // 0..63
    int d0 = (blk & 15) << 1;
    size_t rowa = ((size_t)bh * 32 + d0) * NSEQ;
    size_t rowb = rowa + NSEQ;
    for (int f = threadIdx.x; f < NSEQ; f += blockDim.x) {
        float2 pa = g_P1[rowa + f];
        float2 pb = g_P1[rowb + f];
        int r = __brev((unsigned)f) >> 20;
        z[r] = make_float2(pa.x - pb.y, pa.y + pb.x);
    }
    __syncthreads();
    fft4096<1>(z);
    const float s = 1.0f / (float)NSEQ;
    for (int n = threadIdx.x; n < NSEQ; n += blockDim.x) {
        g_ATTt[rowa + n] = z[n].x * s;
        g_ATTt[rowb + n] = z[n].y * s;
    }
}

// ---------------- epilogue: softmax(head), gate, residual, LayerNorm -------
__global__ void epilogue_kernel(const float* __restrict__ Vin,
                                const float* __restrict__ gamma,
                                const float* __restrict__ beta,
                                float* __restrict__ Out) {
    int t = blockIdx.x;
    int c = threadIdx.x;              // 256 threads, warp == head
    size_t idx = (size_t)t * 256 + c;
    float a = g_ATT[idx];
    float m = a;
#pragma unroll
    for (int o = 16; o; o >>= 1) m = fmaxf(m, __shfl_xor_sync(0xffffffffu, m, o));
    float e = __expf(a - m);
    float s = e;
#pragma unroll
    for (int o = 16; o; o >>= 1) s += __shfl_xor_sync(0xffffffffu, s, o);
    float g = g_VL[idx] * (e / s) + Vin[idx];

    float s1 = g, s2 = g * g;
#pragma unroll
    for (int o = 16; o; o >>= 1) {
        s1 += __shfl_xor_sync(0xffffffffu, s1, o);
        s2 += __shfl_xor_sync(0xffffffffu, s2, o);
    }
    __shared__ float r1[8], r2[8];
    int w = c >> 5, lane = c & 31;
    if (lane == 0) { r1[w] = s1; r2[w] = s2; }
    __syncthreads();
    float t1 = 0.f, t2 = 0.f;
#pragma unroll
    for (int i = 0; i < 8; i++) { t1 += r1[i]; t2 += r2[i]; }
    float mu  = t1 * (1.0f / 256.0f);
    float var = t2 * (1.0f / 256.0f) - mu * mu;
    Out[idx] = (g - mu) * rsqrtf(var + 1e-5f) * gamma[c] + beta[c];
}

// ---------------- launch ----------------------------------------------------
extern "C" void kernel_launch(void* const* d_in, const int* in_sizes, int n_in,
                              void* d_out, int out_size) {
    const float* q     = (const float*)d_in[0];
    const float* k     = (const float*)d_in[1];
    const float* v     = (const float*)d_in[2];
    const float* Wq    = (const float*)d_in[3];
    const float* bq    = (const float*)d_in[4];
    const float* Wk    = (const float*)d_in[5];
    const float* bk    = (const float*)d_in[6];
    const float* Wv    = (const float*)d_in[7];
    const float* bv    = (const float*)d_in[8];
    const float* gamma = (const float*)d_in[9];
    const float* beta  = (const float*)d_in[10];
    float* out = (float*)d_out;

    init_tw_kernel<<<2, 1024>>>();

    dim3 gg(TOK / 128, 256 / 64);
    proj_gemm_kernel<<<gg, 256>>>(q, Wq, bq, 0);
    proj_gemm_kernel<<<gg, 256>>>(k, Wk, bk, 1);
    proj_gemm_kernel<<<gg, 256>>>(v, Wv, bv, 2);

    transpose_kernel<<<dim3(NSEQ / 32, 256 / 32, 16), dim3(32, 8)>>>(0);

    fft_fwd_kernel<<<BATCH * 256, 512>>>();

    dconv_kernel<<<dim3(NSEQ / 64, BATCH * HEADS), 512>>>();

    fft_inv_kernel<<<BATCH * HEADS * (HD / 2), 512>>>();

    transpose_kernel<<<dim3(NSEQ / 32, 256 / 32, 8), dim3(32, 8)>>>(1);

    epilogue_kernel<<<TOK, 256>>>(v, gamma, beta, out);
}

// round 2
// speedup vs baseline: 1.2934x; 1.2934x over previous
#include <cuda_runtime.h>
#include <cstdint>

// Problem constants
#define BATCH 8
#define NSEQ  4096
#define CH    256
#define HEADS 8
#define HD    32
#define TOK   (BATCH * NSEQ)          // 32768 tokens
#define ELEMS (TOK * CH)              // 8,388,608

// ---------------- scratch (device globals; no allocation allowed) ----------
__device__ float  g_QLt[ELEMS];       // channel-major [b,c,n]
__device__ float  g_KLt[ELEMS];
__device__ float  g_VL [ELEMS];       // token-major [b,n,c]
__device__ float2 g_Q1 [ELEMS];       // seq-spectra, layout [(b*256+c), f]
__device__ float2 g_K1 [ELEMS];
__device__ float2 g_P1 [ELEMS];
__device__ float  g_ATTt[ELEMS];      // [b,c,n]
__device__ float  g_ATT [ELEMS];      // [b,n,c]
__device__ float2 g_tw [4096];        // exp(-2*pi*i*m/4096), m=0..4095

// ---------------- twiddle init ---------------------------------------------
__global__ void init_tw_kernel() {
    int j = blockIdx.x * blockDim.x + threadIdx.x;
    if (j < 4096) {
        double a = -2.0 * 3.14159265358979323846 * (double)j / 4096.0;
        g_tw[j] = make_float2((float)cos(a), (float)sin(a));
    }
}

// ---------------- complex helpers ------------------------------------------
struct C { float x, y; };
__device__ __forceinline__ C cadd(C a, C b) { return {a.x + b.x, a.y + b.y}; }
__device__ __forceinline__ C csub(C a, C b) { return {a.x - b.x, a.y - b.y}; }
__device__ __forceinline__ C cmul(C a, C b) {
    return {a.x * b.x - a.y * b.y, a.x * b.y + a.y * b.x};
}
// multiply by -i (fwd) / +i (inv)
template <int INV> __device__ __forceinline__ C crot(C a) {
    return INV ? C{-a.y, a.x} : C{a.y, -a.x};
}
template <int INV> __device__ __forceinline__ C tw(int m) {
    float2 w = g_tw[m];
    return INV ? C{w.x, -w.y} : C{w.x, w.y};
}

// ---------------- in-register 8-point DFT ----------------------------------
template <int INV>
__device__ __forceinline__ void dft8(C a[8]) {
    const float S = 0.70710678118654752440f;
    // even part: a0,a2,a4,a6
    C t0 = cadd(a[0], a[4]), t1 = csub(a[0], a[4]);
    C t2 = cadd(a[2], a[6]), t3 = csub(a[2], a[6]);
    C E0 = cadd(t0, t2), E2 = csub(t0, t2);
    C E1 = cadd(t1, crot<INV>(t3)), E3 = csub(t1, crot<INV>(t3));
    // odd part: a1,a3,a5,a7
    C u0 = cadd(a[1], a[5]), u1 = csub(a[1], a[5]);
    C u2 = cadd(a[3], a[7]), u3 = csub(a[3], a[7]);
    C O0 = cadd(u0, u2), O2 = csub(u0, u2);
    C O1 = cadd(u1, crot<INV>(u3)), O3 = csub(u1, crot<INV>(u3));
    // w8^1 = S*(1 -/+ i), w8^2 = -/+ i, w8^3 = -S*(1 +/- i)
    C w1 = INV ? C{S, S} : C{S, -S};
    C w3 = INV ? C{-S, S} : C{-S, -S};
    C o1 = cmul(w1, O1);
    C o2 = crot<INV>(O2);
    C o3 = cmul(w3, O3);
    a[0] = cadd(E0, O0); a[4] = csub(E0, O0);
    a[1] = cadd(E1, o1); a[5] = csub(E1, o1);
    a[2] = cadd(E2, o2); a[6] = csub(E2, o2);
    a[3] = cadd(E3, o3); a[7] = csub(E3, o3);
}

// ---------------- Stockham radix-8 4096-pt FFT core ------------------------
// 512 threads. On entry a[r] = x[t + 512 r] (natural order).
// On exit a[k] = X[t + 512 k] (natural order). Uses sm[] (padded, 4608 float2).
#define SM_IDX(i) ((i) + ((i) >> 3))

template <int INV>
__device__ __forceinline__ void fft_stages(C a[8], float2* sm) {
    const int t = threadIdx.x;
    // ---- stage 0: n=4096, s=1, p=t, q=0
    dft8<INV>(a);
#pragma unroll
    for (int k = 1; k < 8; k++) a[k] = cmul(a[k], tw<INV>(t * k));
#pragma unroll
    for (int k = 0; k < 8; k++) { C v = a[k]; sm[SM_IDX(8 * t + k)] = make_float2(v.x, v.y); }
    __syncthreads();
    // ---- stage 1: n=512, s=8
    {
#pragma unroll
        for (int r = 0; r < 8; r++) { float2 v = sm[SM_IDX(t + 512 * r)]; a[r] = {v.x, v.y}; }
        __syncthreads();
        dft8<INV>(a);
        int p = t >> 3, q = t & 7;
#pragma unroll
        for (int k = 1; k < 8; k++) a[k] = cmul(a[k], tw<INV>(8 * p * k));
#pragma unroll
        for (int k = 0; k < 8; k++) { C v = a[k]; sm[SM_IDX(q + 64 * p + 8 * k)] = make_float2(v.x, v.y); }
        __syncthreads();
    }
    // ---- stage 2: n=64, s=64
    {
#pragma unroll
        for (int r = 0; r < 8; r++) { float2 v = sm[SM_IDX(t + 512 * r)]; a[r] = {v.x, v.y}; }
        __syncthreads();
        dft8<INV>(a);
        int p = t >> 6, q = t & 63;
#pragma unroll
        for (int k = 1; k < 8; k++) a[k] = cmul(a[k], tw<INV>(64 * p * k));
#pragma unroll
        for (int k = 0; k < 8; k++) { C v = a[k]; sm[SM_IDX(q + 512 * p + 64 * k)] = make_float2(v.x, v.y); }
        __syncthreads();
    }
    // ---- stage 3: n=8, s=512, no twiddle
#pragma unroll
    for (int r = 0; r < 8; r++) { float2 v = sm[SM_IDX(t + 512 * r)]; a[r] = {v.x, v.y}; }
    dft8<INV>(a);
    // a[k] = X[t + 512k]; NOTE: caller must __syncthreads before reusing sm.
}

// ---------------- projection GEMM: Out = X @ W^T + b -----------------------
// M=32768, N=256, K=256.  BM=128, BN=64, BK=16, 256 threads, 8x4 per thread.
// which 0/1: output channel-major [b,c,n] (fused transpose); which 2: token-major.
__global__ void proj_gemm_kernel(const float* __restrict__ X,
                                 const float* __restrict__ W,
                                 const float* __restrict__ bias,
                                 int which) {
    __shared__ union {
        struct { float Xs[16][128]; float Ws[16][64]; } op;
        float tr[64][133];
    } smu;
    int tid = threadIdx.x;
    int bm = blockIdx.x * 128;
    int bn = blockIdx.y * 64;
    int tx = tid & 15;   // n dir (16 * 4 = 64)
    int ty = tid >> 4;   // m dir (16 * 8 = 128)
    float acc[8][4];
#pragma unroll
    for (int i = 0; i < 8; i++)
#pragma unroll
        for (int j = 0; j < 4; j++) acc[i][j] = 0.f;

    for (int k0 = 0; k0 < 256; k0 += 16) {
#pragma unroll
        for (int i = 0; i < 2; i++) {
            int v = tid + i * 256;           // 0..511
            int row = v >> 2;                // 0..127
            int c4  = (v & 3) * 4;           // 0,4,8,12
            float4 x = *(const float4*)(X + (size_t)(bm + row) * 256 + k0 + c4);
            smu.op.Xs[c4 + 0][row] = x.x; smu.op.Xs[c4 + 1][row] = x.y;
            smu.op.Xs[c4 + 2][row] = x.z; smu.op.Xs[c4 + 3][row] = x.w;
        }
        {
            int row = tid >> 2;              // 0..63
            int c4  = (tid & 3) * 4;
            float4 w = *(const float4*)(W + (size_t)(bn + row) * 256 + k0 + c4);
            smu.op.Ws[c4 + 0][row] = w.x; smu.op.Ws[c4 + 1][row] = w.y;
            smu.op.Ws[c4 + 2][row] = w.z; smu.op.Ws[c4 + 3][row] = w.w;
        }
        __syncthreads();
#pragma unroll
        for (int k = 0; k < 16; k++) {
            float a[8], bb[4];
#pragma unroll
            for (int i = 0; i < 8; i++) a[i] = smu.op.Xs[k][ty * 8 + i];
#pragma unroll
            for (int j = 0; j < 4; j++) bb[j] = smu.op.Ws[k][tx * 4 + j];
#pragma unroll
            for (int i = 0; i < 8; i++)
#pragma unroll
                for (int j = 0; j < 4; j++) acc[i][j] = fmaf(a[i], bb[j], acc[i][j]);
        }
        __syncthreads();
    }
    float4 b4 = *(const float4*)(bias + bn + tx * 4);

    if (which == 2) {
        // token-major direct write
#pragma unroll
        for (int i = 0; i < 8; i++) {
            int m = bm + ty * 8 + i;
            float4 o;
            o.x = acc[i][0] + b4.x; o.y = acc[i][1] + b4.y;
            o.z = acc[i][2] + b4.z; o.w = acc[i][3] + b4.w;
            *(float4*)(g_VL + (size_t)m * 256 + bn + tx * 4) = o;
        }
        return;
    }
    // channel-major: stage through smem transpose (tile fully inside one batch)
    float* Out = (which == 0) ? g_QLt : g_KLt;
    float bs[4] = {b4.x, b4.y, b4.z, b4.w};
#pragma unroll
    for (int i = 0; i < 8; i++)
#pragma unroll
        for (int j = 0; j < 4; j++)
            smu.tr[tx * 4 + j][ty * 8 + i] = acc[i][j] + bs[j];
    __syncthreads();
    int b  = bm >> 12;
    int n0 = bm & 4095;
    int row = tid >> 2;          // channel within tile, 0..63
    int seg = tid & 3;           // token quarter
    float* dst = Out + ((size_t)(b * 256 + bn + row)) * NSEQ + n0 + seg * 32;
    const float* src = &smu.tr[row][seg * 32];
#pragma unroll
    for (int jj = 0; jj < 8; jj++) {
        float4 o;
        o.x = src[jj * 4 + 0]; o.y = src[jj * 4 + 1];
        o.z = src[jj * 4 + 2]; o.w = src[jj * 4 + 3];
        *(float4*)(dst + jj * 4) = o;
    }
}

// ---------------- batched transpose ATTt [b,c,n] -> ATT [b,n,c] ------------
__global__ void transpose_kernel() {
    __shared__ float tile[32][33];
    int n0 = blockIdx.x * 32;
    int c0 = blockIdx.y * 32;
    int tx = threadIdx.x, ty = threadIdx.y;
    int b = blockIdx.z;
#pragma unroll
    for (int j = 0; j < 32; j += 8)
        tile[ty + j][tx] = g_ATTt[((size_t)b * 256 + c0 + ty + j) * NSEQ + n0 + tx];
    __syncthreads();
#pragma unroll
    for (int j = 0; j < 32; j += 8)
        g_ATT[((size_t)b * NSEQ + n0 + ty + j) * 256 + c0 + tx] = tile[tx][ty + j];
}

// ---------------- forward seq FFT, packed z = ql + i*kl --------------------
__global__ void fft_fwd_kernel() {
    __shared__ float2 sm[4608];
    int blk = blockIdx.x;             // 0..2047  (b*256 + c)
    size_t col = (size_t)blk * NSEQ;
    int t = threadIdx.x;
    C a[8];
#pragma unroll
    for (int r = 0; r < 8; r++) {
        int n = t + 512 * r;
        a[r] = { g_QLt[col + n], g_KLt[col + n] };
    }
    fft_stages<0>(a, sm);
    __syncthreads();                   // stage-3 reads done before reuse
#pragma unroll
    for (int k = 0; k < 8; k++) sm[SM_IDX(t + 512 * k)] = make_float2(a[k].x, a[k].y);
    __syncthreads();
#pragma unroll
    for (int k = 0; k < 8; k++) {
        int f = t + 512 * k;
        int g = (NSEQ - f) & (NSEQ - 1);
        float2 zf = make_float2(a[k].x, a[k].y);
        float2 zg = sm[SM_IDX(g)];
        g_Q1[col + f] = make_float2(0.5f * (zf.x + zg.x), 0.5f * (zf.y - zg.y));
        g_K1[col + f] = make_float2(0.5f * (zf.y + zg.y), 0.5f * (zg.x - zf.x));
    }
}

// ---------------- per-frequency circular conv over head_dim (32) -----------
__global__ void dconv_kernel() {
    __shared__ float Qre[32][65], Qim[32][65], Kre[32][65], Kim[32][65];
    int f0 = blockIdx.x * 64;
    int bh = blockIdx.y;              // 0..63
    size_t base = (size_t)bh * 32 * NSEQ;
    int tid = threadIdx.x;
#pragma unroll
    for (int i = 0; i < 2; i++) {
        int vv = tid + i * 512;       // 0..1023
        int d  = vv >> 5;             // 0..31
        int j  = vv & 31;             // float4 index -> 2 freqs
        const float4* sq = (const float4*)(g_Q1 + base + (size_t)d * NSEQ + f0);
        const float4* sk = (const float4*)(g_K1 + base + (size_t)d * NSEQ + f0);
        float4 x = sq[j];
        Qre[d][2 * j] = x.x; Qim[d][2 * j] = x.y;
        Qre[d][2 * j + 1] = x.z; Qim[d][2 * j + 1] = x.w;
        float4 y = sk[j];
        Kre[d][2 * j] = y.x; Kim[d][2 * j] = y.y;
        Kre[d][2 * j + 1] = y.z; Kim[d][2 * j + 1] = y.w;
    }
    __syncthreads();
    int w = tid >> 5, lane = tid & 31;
#pragma unroll
    for (int rep = 0; rep < 4; rep++) {
        int f = w + rep * 16;
        float qr = Qre[lane][f], qi = Qim[lane][f];
        float kr = Kre[lane][f], ki = Kim[lane][f];
        float ar = 0.f, ai = 0.f;
#pragma unroll
        for (int e = 0; e < 32; e++) {
            float qer = __shfl_sync(0xffffffffu, qr, e);
            float qei = __shfl_sync(0xffffffffu, qi, e);
            int srcl = (lane - e) & 31;
            float ker = __shfl_sync(0xffffffffu, kr, srcl);
            float kei = __shfl_sync(0xffffffffu, ki, srcl);
            ar = fmaf(qer, ker, fmaf(-qei, kei, ar));
            ai = fmaf(qer, kei, fmaf(qei, ker, ai));
        }
        Qre[lane][f] = ar;
        Qim[lane][f] = ai;
    }
    __syncthreads();
#pragma unroll
    for (int i = 0; i < 2; i++) {
        int vv = tid + i * 512;
        int d  = vv >> 5;
        int j  = vv & 31;
        float4* dst = (float4*)(g_P1 + base + (size_t)d * NSEQ + f0);
        float4 x;
        x.x = Qre[d][2 * j];     x.y = Qim[d][2 * j];
        x.z = Qre[d][2 * j + 1]; x.w = Qim[d][2 * j + 1];
        dst[j] = x;
    }
}

// ---------------- inverse seq FFT, packed pair of d-columns ----------------
__global__ void fft_inv_kernel() {
    __shared__ float2 sm[4608];
    int blk = blockIdx.x;             // 0..1023
    int bh = blk >> 4;                // 0..63
    int d0 = (blk & 15) << 1;
    size_t rowa = ((size_t)bh * 32 + d0) * NSEQ;
    size_t rowb = rowa + NSEQ;
    int t = threadIdx.x;
    C a[8];
#pragma unroll
    for (int r = 0; r < 8; r++) {
        int f = t + 512 * r;
        float2 pa = g_P1[rowa + f];
        float2 pb = g_P1[rowb + f];
        a[r] = { pa.x - pb.y, pa.y + pb.x };
    }
    fft_stages<1>(a, sm);
    const float s = 1.0f / (float)NSEQ;
#pragma unroll
    for (int k = 0; k < 8; k++) {
        int n = t + 512 * k;
        g_ATTt[rowa + n] = a[k].x * s;
        g_ATTt[rowb + n] = a[k].y * s;
    }
}

// ---------------- epilogue: softmax(head), gate, residual, LayerNorm -------
__global__ void epilogue_kernel(const float* __restrict__ Vin,
                                const float* __restrict__ gamma,
                                const float* __restrict__ beta,
                                float* __restrict__ Out) {
    int t = blockIdx.x;
    int c = threadIdx.x;              // 256 threads, warp == head
    size_t idx = (size_t)t * 256 + c;
    float a = g_ATT[idx];
    float m = a;
#pragma unroll
    for (int o = 16; o; o >>= 1) m = fmaxf(m, __shfl_xor_sync(0xffffffffu, m, o));
    float e = __expf(a - m);
    float s = e;
#pragma unroll
    for (int o = 16; o; o >>= 1) s += __shfl_xor_sync(0xffffffffu, s, o);
    float g = g_VL[idx] * (e / s) + Vin[idx];

    float s1 = g, s2 = g * g;
#pragma unroll
    for (int o = 16; o; o >>= 1) {
        s1 += __shfl_xor_sync(0xffffffffu, s1, o);
        s2 += __shfl_xor_sync(0xffffffffu, s2, o);
    }
    __shared__ float r1[8], r2[8];
    int w = c >> 5, lane = c & 31;
    if (lane == 0) { r1[w] = s1; r2[w] = s2; }
    __syncthreads();
    float t1 = 0.f, t2 = 0.f;
#pragma unroll
    for (int i = 0; i < 8; i++) { t1 += r1[i]; t2 += r2[i]; }
    float mu  = t1 * (1.0f / 256.0f);
    float var = t2 * (1.0f / 256.0f) - mu * mu;
    Out[idx] = (g - mu) * rsqrtf(var + 1e-5f) * gamma[c] + beta[c];
}

// ---------------- launch ----------------------------------------------------
extern "C" void kernel_launch(void* const* d_in, const int* in_sizes, int n_in,
                              void* d_out, int out_size) {
    const float* q     = (const float*)d_in[0];
    const float* k     = (const float*)d_in[1];
    const float* v     = (const float*)d_in[2];
    const float* Wq    = (const float*)d_in[3];
    const float* bq    = (const float*)d_in[4];
    const float* Wk    = (const float*)d_in[5];
    const float* bk    = (const float*)d_in[6];
    const float* Wv    = (const float*)d_in[7];
    const float* bv    = (const float*)d_in[8];
    const float* gamma = (const float*)d_in[9];
    const float* beta  = (const float*)d_in[10];
    float* out = (float*)d_out;

    init_tw_kernel<<<4, 1024>>>();

    dim3 gg(TOK / 128, 256 / 64);
    proj_gemm_kernel<<<gg, 256>>>(q, Wq, bq, 0);
    proj_gemm_kernel<<<gg, 256>>>(k, Wk, bk, 1);
    proj_gemm_kernel<<<gg, 256>>>(v, Wv, bv, 2);

    fft_fwd_kernel<<<BATCH * 256, 512>>>();

    dconv_kernel<<<dim3(NSEQ / 64, BATCH * HEADS), 512>>>();

    fft_inv_kernel<<<BATCH * HEADS * (HD / 2), 512>>>();

    transpose_kernel<<<dim3(NSEQ / 32, 256 / 32, 8), dim3(32, 8)>>>();

    epilogue_kernel<<<TOK, 256>>>(v, gamma, beta, out);
}

// round 6
// speedup vs baseline: 1.9091x; 1.4761x over previous
#include <cuda_runtime.h>
#include <cuda_bf16.h>
#include <cstdint>

// Problem constants
#define BATCH 8
#define NSEQ  4096
#define CH    256
#define HEADS 8
#define HD    32
#define TOK   (BATCH * NSEQ)          // 32768 tokens
#define ELEMS (TOK * CH)              // 8,388,608

// ---------------- scratch (device globals; no allocation allowed) ----------
__device__ float  g_QLt[ELEMS];       // channel-major [b,c,n]
__device__ float  g_KLt[ELEMS];
__device__ float  g_VL [ELEMS];       // token-major [b,n,c]
__device__ float2 g_Q1 [ELEMS];       // seq-spectra, layout [(b*256+c), f]
__device__ float2 g_K1 [ELEMS];
__device__ float2 g_P1 [ELEMS];
__device__ float  g_ATTt[ELEMS];      // [b,c,n]
__device__ float  g_ATT [ELEMS];      // [b,n,c]
__device__ float2 g_tw [4096];        // exp(-2*pi*i*m/4096)

// ---------------- twiddle init ---------------------------------------------
__global__ void init_tw_kernel() {
    int j = blockIdx.x * blockDim.x + threadIdx.x;
    if (j < 4096) {
        double a = -2.0 * 3.14159265358979323846 * (double)j / 4096.0;
        g_tw[j] = make_float2((float)cos(a), (float)sin(a));
    }
}

// ===================== warp-MMA helpers (sm_80+ baseline PTX) ===============
__device__ __forceinline__ uint32_t smem_u32(const void* p) {
    uint32_t a;
    asm("{ .reg .u64 t; cvta.to.shared.u64 t, %1; cvt.u32.u64 %0, t; }"
        : "=r"(a) : "l"(p));
    return a;
}
__device__ __forceinline__ void ldm_x4(uint32_t addr, uint32_t r[4]) {
    asm volatile("ldmatrix.sync.aligned.m8n8.x4.shared.b16 {%0,%1,%2,%3}, [%4];"
                 : "=r"(r[0]), "=r"(r[1]), "=r"(r[2]), "=r"(r[3]) : "r"(addr));
}
__device__ __forceinline__ void mma16816(float c[4], const uint32_t a[4],
                                         const uint32_t b[2]) {
    asm volatile("mma.sync.aligned.m16n8k16.row.col.f32.bf16.bf16.f32 "
                 "{%0,%1,%2,%3}, {%4,%5,%6,%7}, {%8,%9}, {%0,%1,%2,%3};"
                 : "+f"(c[0]), "+f"(c[1]), "+f"(c[2]), "+f"(c[3])
                 : "r"(a[0]), "r"(a[1]), "r"(a[2]), "r"(a[3]),
                   "r"(b[0]), "r"(b[1]));
}

// ===================== tensor-core projection GEMM ==========================
// Out[m,n] = sum_k X[m,k] * W[n,k] + bias[n]
// M=32768, N=256, K=256. CTA tile 128x128. bf16 split: D = Ah*Bh + Al*Bh + Ah*Bl.
// K chunks of 32 in smem, row stride 40 bf16 (80 B) -> ldmatrix conflict-free.
#define PSTR 40
#define PJ_ARR (128 * PSTR)           // bf16 elements per operand part

__device__ __forceinline__ void split_store(__nv_bfloat16* hb, __nv_bfloat16* lb,
                                            int row, int kl, float4 x) {
    int off = row * PSTR + kl;
    __nv_bfloat16 h0 = __float2bfloat16(x.x);
    __nv_bfloat16 h1 = __float2bfloat16(x.y);
    __nv_bfloat16 h2 = __float2bfloat16(x.z);
    __nv_bfloat16 h3 = __float2bfloat16(x.w);
    uint2 hv;
    hv.x = ((uint32_t)__bfloat16_as_ushort(h1) << 16) | __bfloat16_as_ushort(h0);
    hv.y = ((uint32_t)__bfloat16_as_ushort(h3) << 16) | __bfloat16_as_ushort(h2);
    *(uint2*)(hb + off) = hv;
    __nv_bfloat16 l0 = __float2bfloat16(x.x - __bfloat162float(h0));
    __nv_bfloat16 l1 = __float2bfloat16(x.y - __bfloat162float(h1));
    __nv_bfloat16 l2 = __float2bfloat16(x.z - __bfloat162float(h2));
    __nv_bfloat16 l3 = __float2bfloat16(x.w - __bfloat162float(h3));
    uint2 lv;
    lv.x = ((uint32_t)__bfloat16_as_ushort(l1) << 16) | __bfloat16_as_ushort(l0);
    lv.y = ((uint32_t)__bfloat16_as_ushort(l3) << 16) | __bfloat16_as_ushort(l2);
    *(uint2*)(lb + off) = lv;
}

__global__ void __launch_bounds__(256, 2)
proj_mma_kernel(const float* __restrict__ q, const float* __restrict__ k,
                const float* __restrict__ v,
                const float* __restrict__ Wq, const float* __restrict__ bq,
                const float* __restrict__ Wk, const float* __restrict__ bk,
                const float* __restrict__ Wv, const float* __restrict__ bv) {
    __shared__ __align__(16) union {
        struct {
            __nv_bfloat16 AH[PJ_ARR], AL[PJ_ARR], BH[PJ_ARR], BL[PJ_ARR];
        } op;
        float tr[64 * 132];
    } sm;

    int which = blockIdx.z;
    const float* X    = (which == 0) ? q  : (which == 1) ? k  : v;
    const float* W    = (which == 0) ? Wq : (which == 1) ? Wk : Wv;
    const float* bias = (which == 0) ? bq : (which == 1) ? bk : bv;
    int bm = blockIdx.x * 128;
    int bn = blockIdx.y * 128;
    int tid = threadIdx.x, wid = tid >> 5, lane = tid & 31;
    int wm = wid & 3, wn = wid >> 2;            // 4 warps in M, 2 in N
    int m0 = wm * 32, n0w = wn * 64;
    int g = lane >> 2, t4 = lane & 3;

    uint32_t uAH = smem_u32(sm.op.AH);
    uint32_t uAL = smem_u32(sm.op.AL);
    uint32_t uBH = smem_u32(sm.op.BH);
    uint32_t uBL = smem_u32(sm.op.BL);

    float acc[2][8][4];
#pragma unroll
    for (int mi = 0; mi < 2; mi++)
#pragma unroll
        for (int nj = 0; nj < 8; nj++)
#pragma unroll
            for (int e = 0; e < 4; e++) acc[mi][nj][e] = 0.f;

    // A-frag address: row = m0 + mi*16 + (lane&15), k = kk + (lane>>4)*8
    int a_row = (lane & 15);
    int a_kh  = (lane >> 4) * 8;
    // B-frag address: n = n0w + nj2*16 + (lane>>4)*8 + (lane&7), k = kk + ((lane>>3)&1)*8
    int b_n   = (lane >> 4) * 8 + (lane & 7);
    int b_kh  = ((lane >> 3) & 1) * 8;

    for (int chunk = 0; chunk < 8; chunk++) {
        int k0 = chunk * 32;
        // ---- load + split-convert chunk ----
#pragma unroll
        for (int i = 0; i < 4; i++) {
            int idx = tid + i * 256;          // 0..1023
            int row = idx >> 3;               // 0..127
            int kl  = (idx & 7) * 4;          // 0..28
            float4 x = *(const float4*)(X + (size_t)(bm + row) * 256 + k0 + kl);
            split_store(sm.op.AH, sm.op.AL, row, kl, x);
            float4 w = *(const float4*)(W + (size_t)(bn + row) * 256 + k0 + kl);
            split_store(sm.op.BH, sm.op.BL, row, kl, w);
        }
        __syncthreads();
        // ---- compute: 2 k-steps of 16 ----
#pragma unroll
        for (int ks = 0; ks < 2; ks++) {
            int kk = ks * 16;
            uint32_t ah[2][4], al[2][4], bb[8][2];
#pragma unroll
            for (int mi = 0; mi < 2; mi++) {
                uint32_t off = (uint32_t)((m0 + mi * 16 + a_row) * PSTR + kk + a_kh) * 2;
                ldm_x4(uAH + off, ah[mi]);
                ldm_x4(uAL + off, al[mi]);
            }
#pragma unroll
            for (int nj2 = 0; nj2 < 4; nj2++) {
                uint32_t off = (uint32_t)((n0w + nj2 * 16 + b_n) * PSTR + kk + b_kh) * 2;
                uint32_t r[4];
                ldm_x4(uBH + off, r);
                bb[2 * nj2][0] = r[0]; bb[2 * nj2][1] = r[1];
                bb[2 * nj2 + 1][0] = r[2]; bb[2 * nj2 + 1][1] = r[3];
            }
#pragma unroll
            for (int mi = 0; mi < 2; mi++)
#pragma unroll
                for (int nj = 0; nj < 8; nj++) mma16816(acc[mi][nj], ah[mi], bb[nj]);
#pragma unroll
            for (int mi = 0; mi < 2; mi++)
#pragma unroll
                for (int nj = 0; nj < 8; nj++) mma16816(acc[mi][nj], al[mi], bb[nj]);
            // reload B with lo part, reuse ah
#pragma unroll
            for (int nj2 = 0; nj2 < 4; nj2++) {
                uint32_t off = (uint32_t)((n0w + nj2 * 16 + b_n) * PSTR + kk + b_kh) * 2;
                uint32_t r[4];
                ldm_x4(uBL + off, r);
                bb[2 * nj2][0] = r[0]; bb[2 * nj2][1] = r[1];
                bb[2 * nj2 + 1][0] = r[2]; bb[2 * nj2 + 1][1] = r[3];
            }
#pragma unroll
            for (int mi = 0; mi < 2; mi++)
#pragma unroll
                for (int nj = 0; nj < 8; nj++) mma16816(acc[mi][nj], ah[mi], bb[nj]);
        }
        __syncthreads();
    }

    // ---- epilogue ----
    // acc[mi][nj][e]: row m = m0 + mi*16 + g + (e>>1)*8 ; col = n0w + nj*8 + 2*t4 + (e&1)
    if (which == 2) {
        // token-major with bias
#pragma unroll
        for (int mi = 0; mi < 2; mi++)
#pragma unroll
            for (int eh = 0; eh < 2; eh++) {
                int m = bm + m0 + mi * 16 + g + eh * 8;
#pragma unroll
                for (int nj = 0; nj < 8; nj++) {
                    int col = n0w + nj * 8 + 2 * t4;
                    float2 o;
                    o.x = acc[mi][nj][eh * 2 + 0] + bias[bn + col];
                    o.y = acc[mi][nj][eh * 2 + 1] + bias[bn + col + 1];
                    *(float2*)(g_VL + (size_t)m * 256 + bn + col) = o;
                }
            }
        return;
    }
    // Q/K: channel-major via smem transpose, two 64-channel passes
    float* Out = (which == 0) ? g_QLt : g_KLt;
    int b  = bm >> 12;
    int n0 = bm & 4095;
    for (int p = 0; p < 2; p++) {
        __syncthreads();                 // smem free / previous pass flushed
        if (wn == p) {
#pragma unroll
            for (int mi = 0; mi < 2; mi++)
#pragma unroll
                for (int eh = 0; eh < 2; eh++) {
                    int ml = m0 + mi * 16 + g + eh * 8;
#pragma unroll
                    for (int nj = 0; nj < 8; nj++) {
                        int cl = nj * 8 + 2 * t4;
                        sm.tr[(size_t)cl * 132 + ml] =
                            acc[mi][nj][eh * 2 + 0] + bias[bn + n0w + cl];
                        sm.tr[(size_t)(cl + 1) * 132 + ml] =
                            acc[mi][nj][eh * 2 + 1] + bias[bn + n0w + cl + 1];
                    }
                }
        }
        __syncthreads();
        int cl  = tid >> 2;              // 0..63
        int qtr = tid & 3;               // token quarter
        float* dst = Out + ((size_t)(b * 256 + bn + p * 64 + cl)) * NSEQ + n0 + qtr * 32;
        const float* src = sm.tr + (size_t)cl * 132 + qtr * 32;
#pragma unroll
        for (int j = 0; j < 8; j++) {
            float4 o;
            o.x = src[4 * j + 0]; o.y = src[4 * j + 1];
            o.z = src[4 * j + 2]; o.w = src[4 * j + 3];
            *(float4*)(dst + 4 * j) = o;
        }
    }
}

// ---------------- complex helpers ------------------------------------------
struct C { float x, y; };
__device__ __forceinline__ C cadd(C a, C b) { return {a.x + b.x, a.y + b.y}; }
__device__ __forceinline__ C csub(C a, C b) { return {a.x - b.x, a.y - b.y}; }
__device__ __forceinline__ C cmul(C a, C b) {
    return {a.x * b.x - a.y * b.y, a.x * b.y + a.y * b.x};
}
template <int INV> __device__ __forceinline__ C crot(C a) {
    return INV ? C{-a.y, a.x} : C{a.y, -a.x};
}
template <int INV> __device__ __forceinline__ C tw(int m) {
    float2 w = g_tw[m];
    return INV ? C{w.x, -w.y} : C{w.x, w.y};
}

// ---------------- in-register 8-point DFT ----------------------------------
template <int INV>
__device__ __forceinline__ void dft8(C a[8]) {
    const float S = 0.70710678118654752440f;
    C t0 = cadd(a[0], a[4]), t1 = csub(a[0], a[4]);
    C t2 = cadd(a[2], a[6]), t3 = csub(a[2], a[6]);
    C E0 = cadd(t0, t2), E2 = csub(t0, t2);
    C E1 = cadd(t1, crot<INV>(t3)), E3 = csub(t1, crot<INV>(t3));
    C u0 = cadd(a[1], a[5]), u1 = csub(a[1], a[5]);
    C u2 = cadd(a[3], a[7]), u3 = csub(a[3], a[7]);
    C O0 = cadd(u0, u2), O2 = csub(u0, u2);
    C O1 = cadd(u1, crot<INV>(u3)), O3 = csub(u1, crot<INV>(u3));
    C w1 = INV ? C{S, S} : C{S, -S};
    C w3 = INV ? C{-S, S} : C{-S, -S};
    C o1 = cmul(w1, O1);
    C o2 = crot<INV>(O2);
    C o3 = cmul(w3, O3);
    a[0] = cadd(E0, O0); a[4] = csub(E0, O0);
    a[1] = cadd(E1, o1); a[5] = csub(E1, o1);
    a[2] = cadd(E2, o2); a[6] = csub(E2, o2);
    a[3] = cadd(E3, o3); a[7] = csub(E3, o3);
}

// ---------------- Stockham radix-8 4096-pt FFT core ------------------------
#define SM_IDX(i) ((i) + ((i) >> 3))

template <int INV>
__device__ __forceinline__ void fft_stages(C a[8], float2* sm) {
    const int t = threadIdx.x;
    dft8<INV>(a);
#pragma unroll
    for (int k = 1; k < 8; k++) a[k] = cmul(a[k], tw<INV>(t * k));
#pragma unroll
    for (int k = 0; k < 8; k++) { C v = a[k]; sm[SM_IDX(8 * t + k)] = make_float2(v.x, v.y); }
    __syncthreads();
    {
#pragma unroll
        for (int r = 0; r < 8; r++) { float2 v = sm[SM_IDX(t + 512 * r)]; a[r] = {v.x, v.y}; }
        __syncthreads();
        dft8<INV>(a);
        int p = t >> 3, qq = t & 7;
#pragma unroll
        for (int k = 1; k < 8; k++) a[k] = cmul(a[k], tw<INV>(8 * p * k));
#pragma unroll
        for (int k = 0; k < 8; k++) { C v = a[k]; sm[SM_IDX(qq + 64 * p + 8 * k)] = make_float2(v.x, v.y); }
        __syncthreads();
    }
    {
#pragma unroll
        for (int r = 0; r < 8; r++) { float2 v = sm[SM_IDX(t + 512 * r)]; a[r] = {v.x, v.y}; }
        __syncthreads();
        dft8<INV>(a);
        int p = t >> 6, qq = t & 63;
#pragma unroll
        for (int k = 1; k < 8; k++) a[k] = cmul(a[k], tw<INV>(64 * p * k));
#pragma unroll
        for (int k = 0; k < 8; k++) { C v = a[k]; sm[SM_IDX(qq + 512 * p + 64 * k)] = make_float2(v.x, v.y); }
        __syncthreads();
    }
#pragma unroll
    for (int r = 0; r < 8; r++) { float2 v = sm[SM_IDX(t + 512 * r)]; a[r] = {v.x, v.y}; }
    dft8<INV>(a);
}

// ---------------- forward seq FFT, packed z = ql + i*kl --------------------
__global__ void fft_fwd_kernel() {
    __shared__ float2 sm[4608];
    int blk = blockIdx.x;
    size_t col = (size_t)blk * NSEQ;
    int t = threadIdx.x;
    C a[8];
#pragma unroll
    for (int r = 0; r < 8; r++) {
        int n = t + 512 * r;
        a[r] = { g_QLt[col + n], g_KLt[col + n] };
    }
    fft_stages<0>(a, sm);
    __syncthreads();
#pragma unroll
    for (int k = 0; k < 8; k++) sm[SM_IDX(t + 512 * k)] = make_float2(a[k].x, a[k].y);
    __syncthreads();
#pragma unroll
    for (int k = 0; k < 8; k++) {
        int f = t + 512 * k;
        int g = (NSEQ - f) & (NSEQ - 1);
        float2 zf = make_float2(a[k].x, a[k].y);
        float2 zg = sm[SM_IDX(g)];
        g_Q1[col + f] = make_float2(0.5f * (zf.x + zg.x), 0.5f * (zf.y - zg.y));
        g_K1[col + f] = make_float2(0.5f * (zf.y + zg.y), 0.5f * (zg.x - zf.x));
    }
}

// ---------------- per-frequency circular conv over head_dim (32) -----------
__global__ void dconv_kernel() {
    __shared__ float Qre[32][65], Qim[32][65], Kre[32][65], Kim[32][65];
    int f0 = blockIdx.x * 64;
    int bh = blockIdx.y;
    size_t base = (size_t)bh * 32 * NSEQ;
    int tid = threadIdx.x;
#pragma unroll
    for (int i = 0; i < 2; i++) {
        int vv = tid + i * 512;
        int d  = vv >> 5;
        int j  = vv & 31;
        const float4* sq = (const float4*)(g_Q1 + base + (size_t)d * NSEQ + f0);
        const float4* sk = (const float4*)(g_K1 + base + (size_t)d * NSEQ + f0);
        float4 x = sq[j];
        Qre[d][2 * j] = x.x; Qim[d][2 * j] = x.y;
        Qre[d][2 * j + 1] = x.z; Qim[d][2 * j + 1] = x.w;
        float4 y = sk[j];
        Kre[d][2 * j] = y.x; Kim[d][2 * j] = y.y;
        Kre[d][2 * j + 1] = y.z; Kim[d][2 * j + 1] = y.w;
    }
    __syncthreads();
    int w = tid >> 5, lane = tid & 31;
#pragma unroll
    for (int rep = 0; rep < 4; rep++) {
        int f = w + rep * 16;
        float qr = Qre[lane][f], qi = Qim[lane][f];
        float kr = Kre[lane][f], ki = Kim[lane][f];
        float ar = 0.f, ai = 0.f;
#pragma unroll
        for (int e = 0; e < 32; e++) {
            float qer = __shfl_sync(0xffffffffu, qr, e);
            float qei = __shfl_sync(0xffffffffu, qi, e);
            int srcl = (lane - e) & 31;
            float ker = __shfl_sync(0xffffffffu, kr, srcl);
            float kei = __shfl_sync(0xffffffffu, ki, srcl);
            ar = fmaf(qer, ker, fmaf(-qei, kei, ar));
            ai = fmaf(qer, kei, fmaf(qei, ker, ai));
        }
        Qre[lane][f] = ar;
        Qim[lane][f] = ai;
    }
    __syncthreads();
#pragma unroll
    for (int i = 0; i < 2; i++) {
        int vv = tid + i * 512;
        int d  = vv >> 5;
        int j  = vv & 31;
        float4* dst = (float4*)(g_P1 + base + (size_t)d * NSEQ + f0);
        float4 x;
        x.x = Qre[d][2 * j];     x.y = Qim[d][2 * j];
        x.z = Qre[d][2 * j + 1]; x.w = Qim[d][2 * j + 1];
        dst[j] = x;
    }
}

// ---------------- inverse seq FFT, packed pair of d-columns ----------------
__global__ void fft_inv_kernel() {
    __shared__ float2 sm[4608];
    int blk = blockIdx.x;
    int bh = blk >> 4;
    int d0 = (blk & 15) << 1;
    size_t rowa = ((size_t)bh * 32 + d0) * NSEQ;
    size_t rowb = rowa + NSEQ;
    int t = threadIdx.x;
    C a[8];
#pragma unroll
    for (int r = 0; r < 8; r++) {
        int f = t + 512 * r;
        float2 pa = g_P1[rowa + f];
        float2 pb = g_P1[rowb + f];
        a[r] = { pa.x - pb.y, pa.y + pb.x };
    }
    fft_stages<1>(a, sm);
    const float s = 1.0f / (float)NSEQ;
#pragma unroll
    for (int k = 0; k < 8; k++) {
        int n = t + 512 * k;
        g_ATTt[rowa + n] = a[k].x * s;
        g_ATTt[rowb + n] = a[k].y * s;
    }
}

// ---------------- batched transpose ATTt [b,c,n] -> ATT [b,n,c] ------------
__global__ void transpose_kernel() {
    __shared__ float tile[32][33];
    int n0 = blockIdx.x * 32;
    int c0 = blockIdx.y * 32;
    int tx = threadIdx.x, ty = threadIdx.y;
    int b = blockIdx.z;
#pragma unroll
    for (int j = 0; j < 32; j += 8)
        tile[ty + j][tx] = g_ATTt[((size_t)b * 256 + c0 + ty + j) * NSEQ + n0 + tx];
    __syncthreads();
#pragma unroll
    for (int j = 0; j < 32; j += 8)
        g_ATT[((size_t)b * NSEQ + n0 + ty + j) * 256 + c0 + tx] = tile[tx][ty + j];
}

// ---------------- epilogue: softmax(head), gate, residual, LayerNorm -------
__global__ void epilogue_kernel(const float* __restrict__ Vin,
                                const float* __restrict__ gamma,
                                const float* __restrict__ beta,
                                float* __restrict__ Out) {
    int t = blockIdx.x;
    int c = threadIdx.x;
    size_t idx = (size_t)t * 256 + c;
    float a = g_ATT[idx];
    float m = a;
#pragma unroll
    for (int o = 16; o; o >>= 1) m = fmaxf(m, __shfl_xor_sync(0xffffffffu, m, o));
    float e = __expf(a - m);
    float s = e;
#pragma unroll
    for (int o = 16; o; o >>= 1) s += __shfl_xor_sync(0xffffffffu, s, o);
    float g = g_VL[idx] * (e / s) + Vin[idx];

    float s1 = g, s2 = g * g;
#pragma unroll
    for (int o = 16; o; o >>= 1) {
        s1 += __shfl_xor_sync(0xffffffffu, s1, o);
        s2 += __shfl_xor_sync(0xffffffffu, s2, o);
    }
    __shared__ float r1[8], r2[8];
    int w = c >> 5, lane = c & 31;
    if (lane == 0) { r1[w] = s1; r2[w] = s2; }
    __syncthreads();
    float t1 = 0.f, t2 = 0.f;
#pragma unroll
    for (int i = 0; i < 8; i++) { t1 += r1[i]; t2 += r2[i]; }
    float mu  = t1 * (1.0f / 256.0f);
    float var = t2 * (1.0f / 256.0f) - mu * mu;
    Out[idx] = (g - mu) * rsqrtf(var + 1e-5f) * gamma[c] + beta[c];
}

// ---------------- launch ----------------------------------------------------
extern "C" void kernel_launch(void* const* d_in, const int* in_sizes, int n_in,
                              void* d_out, int out_size) {
    const float* q     = (const float*)d_in[0];
    const float* k     = (const float*)d_in[1];
    const float* v     = (const float*)d_in[2];
    const float* Wq    = (const float*)d_in[3];
    const float* bq    = (const float*)d_in[4];
    const float* Wk    = (const float*)d_in[5];
    const float* bk    = (const float*)d_in[6];
    const float* Wv    = (const float*)d_in[7];
    const float* bv    = (const float*)d_in[8];
    const float* gamma = (const float*)d_in[9];
    const float* beta  = (const float*)d_in[10];
    float* out = (float*)d_out;

    init_tw_kernel<<<4, 1024>>>();

    proj_mma_kernel<<<dim3(TOK / 128, 2, 3), 256>>>(
        q, k, v, Wq, bq, Wk, bk, Wv, bv);

    fft_fwd_kernel<<<BATCH * 256, 512>>>();

    dconv_kernel<<<dim3(NSEQ / 64, BATCH * HEADS), 512>>>();

    fft_inv_kernel<<<BATCH * HEADS * (HD / 2), 512>>>();

    transpose_kernel<<<dim3(NSEQ / 32, 256 / 32, 8), dim3(32, 8)>>>();

    epilogue_kernel<<<TOK, 256>>>(v, gamma, beta, out);
}

// round 12
// speedup vs baseline: 2.1780x; 1.1408x over previous
#include <cuda_runtime.h>
#include <cuda_bf16.h>
#include <cstdint>

// Problem constants
#define BATCH 8
#define NSEQ  4096
#define CH    256
#define HEADS 8
#define HD    32
#define TOK   (BATCH * NSEQ)          // 32768 tokens
#define ELEMS (TOK * CH)              // 8,388,608
#define FMAX  2112                    // spectra stored/computed for f < FMAX

// ---------------- scratch (device globals; no allocation allowed) ----------
__device__ float  g_QLt[ELEMS];       // channel-major [b,c,n]
__device__ float  g_KLt[ELEMS];
__device__ float  g_VL [ELEMS];       // token-major [b,n,c]
__device__ float2 g_Q1 [ELEMS];       // seq-spectra, layout [(b*256+c), f], f<FMAX valid
__device__ float2 g_K1 [ELEMS];
__device__ float2 g_P1 [ELEMS];
__device__ float  g_ATTt[ELEMS];      // [b,c,n]
__device__ float2 g_tw [4096];        // exp(-2*pi*i*m/4096)

// ---------------- twiddle init ---------------------------------------------
__global__ void init_tw_kernel() {
    int j = blockIdx.x * blockDim.x + threadIdx.x;
    if (j < 4096) {
        double a = -2.0 * 3.14159265358979323846 * (double)j / 4096.0;
        g_tw[j] = make_float2((float)cos(a), (float)sin(a));
    }
}

// ===================== warp-MMA helpers (sm_80+ baseline PTX) ===============
__device__ __forceinline__ uint32_t smem_u32(const void* p) {
    uint32_t a;
    asm("{ .reg .u64 t; cvta.to.shared.u64 t, %1; cvt.u32.u64 %0, t; }"
        : "=r"(a) : "l"(p));
    return a;
}
__device__ __forceinline__ void ldm_x4(uint32_t addr, uint32_t r[4]) {
    asm volatile("ldmatrix.sync.aligned.m8n8.x4.shared.b16 {%0,%1,%2,%3}, [%4];"
                 : "=r"(r[0]), "=r"(r[1]), "=r"(r[2]), "=r"(r[3]) : "r"(addr));
}
__device__ __forceinline__ void mma16816(float c[4], const uint32_t a[4],
                                         const uint32_t b[2]) {
    asm volatile("mma.sync.aligned.m16n8k16.row.col.f32.bf16.bf16.f32 "
                 "{%0,%1,%2,%3}, {%4,%5,%6,%7}, {%8,%9}, {%0,%1,%2,%3};"
                 : "+f"(c[0]), "+f"(c[1]), "+f"(c[2]), "+f"(c[3])
                 : "r"(a[0]), "r"(a[1]), "r"(a[2]), "r"(a[3]),
                   "r"(b[0]), "r"(b[1]));
}

// ===================== tensor-core projection GEMM ==========================
// Out[m,n] = sum_k X[m,k] * W[n,k] + bias[n]
// M=32768, N=256, K=256. CTA tile 128x128. bf16 split: D = Ah*Bh + Al*Bh + Ah*Bl.
// K chunks of 32 in smem, row stride 40 bf16 (80 B) -> ldmatrix conflict-free.
#define PSTR 40
#define PJ_ARR (128 * PSTR)           // bf16 elements per operand part

__device__ __forceinline__ void split_store(__nv_bfloat16* hb, __nv_bfloat16* lb,
                                            int row, int kl, float4 x) {
    int off = row * PSTR + kl;
    __nv_bfloat16 h0 = __float2bfloat16(x.x);
    __nv_bfloat16 h1 = __float2bfloat16(x.y);
    __nv_bfloat16 h2 = __float2bfloat16(x.z);
    __nv_bfloat16 h3 = __float2bfloat16(x.w);
    uint2 hv;
    hv.x = ((uint32_t)__bfloat16_as_ushort(h1) << 16) | __bfloat16_as_ushort(h0);
    hv.y = ((uint32_t)__bfloat16_as_ushort(h3) << 16) | __bfloat16_as_ushort(h2);
    *(uint2*)(hb + off) = hv;
    __nv_bfloat16 l0 = __float2bfloat16(x.x - __bfloat162float(h0));
    __nv_bfloat16 l1 = __float2bfloat16(x.y - __bfloat162float(h1));
    __nv_bfloat16 l2 = __float2bfloat16(x.z - __bfloat162float(h2));
    __nv_bfloat16 l3 = __float2bfloat16(x.w - __bfloat162float(h3));
    uint2 lv;
    lv.x = ((uint32_t)__bfloat16_as_ushort(l1) << 16) | __bfloat16_as_ushort(l0);
    lv.y = ((uint32_t)__bfloat16_as_ushort(l3) << 16) | __bfloat16_as_ushort(l2);
    *(uint2*)(lb + off) = lv;
}

__global__ void __launch_bounds__(256, 2)
proj_mma_kernel(const float* __restrict__ q, const float* __restrict__ k,
                const float* __restrict__ v,
                const float* __restrict__ Wq, const float* __restrict__ bq,
                const float* __restrict__ Wk, const float* __restrict__ bk,
                const float* __restrict__ Wv, const float* __restrict__ bv) {
    __shared__ __align__(16) union {
        struct {
            __nv_bfloat16 AH[PJ_ARR], AL[PJ_ARR], BH[PJ_ARR], BL[PJ_ARR];
        } op;
        float tr[64 * 132];
    } sm;

    int which = blockIdx.z;
    const float* X    = (which == 0) ? q  : (which == 1) ? k  : v;
    const float* W    = (which == 0) ? Wq : (which == 1) ? Wk : Wv;
    const float* bias = (which == 0) ? bq : (which == 1) ? bk : bv;
    int bm = blockIdx.x * 128;
    int bn = blockIdx.y * 128;
    int tid = threadIdx.x, wid = tid >> 5, lane = tid & 31;
    int wm = wid & 3, wn = wid >> 2;            // 4 warps in M, 2 in N
    int m0 = wm * 32, n0w = wn * 64;
    int g = lane >> 2, t4 = lane & 3;

    uint32_t uAH = smem_u32(sm.op.AH);
    uint32_t uAL = smem_u32(sm.op.AL);
    uint32_t uBH = smem_u32(sm.op.BH);
    uint32_t uBL = smem_u32(sm.op.BL);

    float acc[2][8][4];
#pragma unroll
    for (int mi = 0; mi < 2; mi++)
#pragma unroll
        for (int nj = 0; nj < 8; nj++)
#pragma unroll
            for (int e = 0; e < 4; e++) acc[mi][nj][e] = 0.f;

    int a_row = (lane & 15);
    int a_kh  = (lane >> 4) * 8;
    int b_n   = (lane >> 4) * 8 + (lane & 7);
    int b_kh  = ((lane >> 3) & 1) * 8;

    for (int chunk = 0; chunk < 8; chunk++) {
        int k0 = chunk * 32;
        // ---- load + split-convert chunk ----
#pragma unroll
        for (int i = 0; i < 4; i++) {
            int idx = tid + i * 256;          // 0..1023
            int row = idx >> 3;               // 0..127
            int kl  = (idx & 7) * 4;          // 0..28
            float4 x = *(const float4*)(X + (size_t)(bm + row) * 256 + k0 + kl);
            split_store(sm.op.AH, sm.op.AL, row, kl, x);
            float4 w = *(const float4*)(W + (size_t)(bn + row) * 256 + k0 + kl);
            split_store(sm.op.BH, sm.op.BL, row, kl, w);
        }
        __syncthreads();
        // ---- compute: 2 k-steps of 16 ----
#pragma unroll
        for (int ks = 0; ks < 2; ks++) {
            int kk = ks * 16;
            uint32_t ah[2][4], al[2][4], bb[8][2];
#pragma unroll
            for (int mi = 0; mi < 2; mi++) {
                uint32_t off = (uint32_t)((m0 + mi * 16 + a_row) * PSTR + kk + a_kh) * 2;
                ldm_x4(uAH + off, ah[mi]);
                ldm_x4(uAL + off, al[mi]);
            }
#pragma unroll
            for (int nj2 = 0; nj2 < 4; nj2++) {
                uint32_t off = (uint32_t)((n0w + nj2 * 16 + b_n) * PSTR + kk + b_kh) * 2;
                uint32_t r[4];
                ldm_x4(uBH + off, r);
                bb[2 * nj2][0] = r[0]; bb[2 * nj2][1] = r[1];
                bb[2 * nj2 + 1][0] = r[2]; bb[2 * nj2 + 1][1] = r[3];
            }
#pragma unroll
            for (int mi = 0; mi < 2; mi++)
#pragma unroll
                for (int nj = 0; nj < 8; nj++) mma16816(acc[mi][nj], ah[mi], bb[nj]);
#pragma unroll
            for (int mi = 0; mi < 2; mi++)
#pragma unroll
                for (int nj = 0; nj < 8; nj++) mma16816(acc[mi][nj], al[mi], bb[nj]);
#pragma unroll
            for (int nj2 = 0; nj2 < 4; nj2++) {
                uint32_t off = (uint32_t)((n0w + nj2 * 16 + b_n) * PSTR + kk + b_kh) * 2;
                uint32_t r[4];
                ldm_x4(uBL + off, r);
                bb[2 * nj2][0] = r[0]; bb[2 * nj2][1] = r[1];
                bb[2 * nj2 + 1][0] = r[2]; bb[2 * nj2 + 1][1] = r[3];
            }
#pragma unroll
            for (int mi = 0; mi < 2; mi++)
#pragma unroll
                for (int nj = 0; nj < 8; nj++) mma16816(acc[mi][nj], ah[mi], bb[nj]);
        }
        __syncthreads();
    }

    // ---- epilogue ----
    if (which == 2) {
#pragma unroll
        for (int mi = 0; mi < 2; mi++)
#pragma unroll
            for (int eh = 0; eh < 2; eh++) {
                int m = bm + m0 + mi * 16 + g + eh * 8;
#pragma unroll
                for (int nj = 0; nj < 8; nj++) {
                    int col = n0w + nj * 8 + 2 * t4;
                    float2 o;
                    o.x = acc[mi][nj][eh * 2 + 0] + bias[bn + col];
                    o.y = acc[mi][nj][eh * 2 + 1] + bias[bn + col + 1];
                    *(float2*)(g_VL + (size_t)m * 256 + bn + col) = o;
                }
            }
        return;
    }
    float* Out = (which == 0) ? g_QLt : g_KLt;
    int b  = bm >> 12;
    int n0 = bm & 4095;
    for (int p = 0; p < 2; p++) {
        __syncthreads();
        if (wn == p) {
#pragma unroll
            for (int mi = 0; mi < 2; mi++)
#pragma unroll
                for (int eh = 0; eh < 2; eh++) {
                    int ml = m0 + mi * 16 + g + eh * 8;
#pragma unroll
                    for (int nj = 0; nj < 8; nj++) {
                        int cl = nj * 8 + 2 * t4;
                        sm.tr[(size_t)cl * 132 + ml] =
                            acc[mi][nj][eh * 2 + 0] + bias[bn + n0w + cl];
                        sm.tr[(size_t)(cl + 1) * 132 + ml] =
                            acc[mi][nj][eh * 2 + 1] + bias[bn + n0w + cl + 1];
                    }
                }
        }
        __syncthreads();
        int cl  = tid >> 2;
        int qtr = tid & 3;
        float* dst = Out + ((size_t)(b * 256 + bn + p * 64 + cl)) * NSEQ + n0 + qtr * 32;
        const float* src = sm.tr + (size_t)cl * 132 + qtr * 32;
#pragma unroll
        for (int j = 0; j < 8; j++) {
            float4 o;
            o.x = src[4 * j + 0]; o.y = src[4 * j + 1];
            o.z = src[4 * j + 2]; o.w = src[4 * j + 3];
            *(float4*)(dst + 4 * j) = o;
        }
    }
}

// ---------------- complex helpers ------------------------------------------
struct C { float x, y; };
__device__ __forceinline__ C cadd(C a, C b) { return {a.x + b.x, a.y + b.y}; }
__device__ __forceinline__ C csub(C a, C b) { return {a.x - b.x, a.y - b.y}; }
__device__ __forceinline__ C cmul(C a, C b) {
    return {a.x * b.x - a.y * b.y, a.x * b.y + a.y * b.x};
}
template <int INV> __device__ __forceinline__ C crot(C a) {
    return INV ? C{-a.y, a.x} : C{a.y, -a.x};
}
template <int INV> __device__ __forceinline__ C tw(int m) {
    float2 w = g_tw[m];
    return INV ? C{w.x, -w.y} : C{w.x, w.y};
}

// ---------------- in-register 8-point DFT ----------------------------------
template <int INV>
__device__ __forceinline__ void dft8(C a[8]) {
    const float S = 0.70710678118654752440f;
    C t0 = cadd(a[0], a[4]), t1 = csub(a[0], a[4]);
    C t2 = cadd(a[2], a[6]), t3 = csub(a[2], a[6]);
    C E0 = cadd(t0, t2), E2 = csub(t0, t2);
    C E1 = cadd(t1, crot<INV>(t3)), E3 = csub(t1, crot<INV>(t3));
    C u0 = cadd(a[1], a[5]), u1 = csub(a[1], a[5]);
    C u2 = cadd(a[3], a[7]), u3 = csub(a[3], a[7]);
    C O0 = cadd(u0, u2), O2 = csub(u0, u2);
    C O1 = cadd(u1, crot<INV>(u3)), O3 = csub(u1, crot<INV>(u3));
    C w1 = INV ? C{S, S} : C{S, -S};
    C w3 = INV ? C{-S, S} : C{-S, -S};
    C o1 = cmul(w1, O1);
    C o2 = crot<INV>(O2);
    C o3 = cmul(w3, O3);
    a[0] = cadd(E0, O0); a[4] = csub(E0, O0);
    a[1] = cadd(E1, o1); a[5] = csub(E1, o1);
    a[2] = cadd(E2, o2); a[6] = csub(E2, o2);
    a[3] = cadd(E3, o3); a[7] = csub(E3, o3);
}

// ---------------- Stockham radix-8 4096-pt FFT core ------------------------
#define SM_IDX(i) ((i) + ((i) >> 3))

template <int INV>
__device__ __forceinline__ void fft_stages(C a[8], float2* sm) {
    const int t = threadIdx.x;
    dft8<INV>(a);
#pragma unroll
    for (int k = 1; k < 8; k++) a[k] = cmul(a[k], tw<INV>(t * k));
#pragma unroll
    for (int k = 0; k < 8; k++) { C v = a[k]; sm[SM_IDX(8 * t + k)] = make_float2(v.x, v.y); }
    __syncthreads();
    {
#pragma unroll
        for (int r = 0; r < 8; r++) { float2 v = sm[SM_IDX(t + 512 * r)]; a[r] = {v.x, v.y}; }
        __syncthreads();
        dft8<INV>(a);
        int p = t >> 3, qq = t & 7;
#pragma unroll
        for (int k = 1; k < 8; k++) a[k] = cmul(a[k], tw<INV>(8 * p * k));
#pragma unroll
        for (int k = 0; k < 8; k++) { C v = a[k]; sm[SM_IDX(qq + 64 * p + 8 * k)] = make_float2(v.x, v.y); }
        __syncthreads();
    }
    {
#pragma unroll
        for (int r = 0; r < 8; r++) { float2 v = sm[SM_IDX(t + 512 * r)]; a[r] = {v.x, v.y}; }
        __syncthreads();
        dft8<INV>(a);
        int p = t >> 6, qq = t & 63;
#pragma unroll
        for (int k = 1; k < 8; k++) a[k] = cmul(a[k], tw<INV>(64 * p * k));
#pragma unroll
        for (int k = 0; k < 8; k++) { C v = a[k]; sm[SM_IDX(qq + 512 * p + 64 * k)] = make_float2(v.x, v.y); }
        __syncthreads();
    }
#pragma unroll
    for (int r = 0; r < 8; r++) { float2 v = sm[SM_IDX(t + 512 * r)]; a[r] = {v.x, v.y}; }
    dft8<INV>(a);
}

// ---------------- forward seq FFT, packed z = ql + i*kl --------------------
// Stores spectra only for f < FMAX (hermitian: f>2048 is conj of mirror).
__global__ void fft_fwd_kernel() {
    __shared__ float2 sm[4608];
    int blk = blockIdx.x;
    size_t col = (size_t)blk * NSEQ;
    int t = threadIdx.x;
    C a[8];
#pragma unroll
    for (int r = 0; r < 8; r++) {
        int n = t + 512 * r;
        a[r] = { g_QLt[col + n], g_KLt[col + n] };
    }
    fft_stages<0>(a, sm);
    __syncthreads();
#pragma unroll
    for (int k = 0; k < 8; k++) sm[SM_IDX(t + 512 * k)] = make_float2(a[k].x, a[k].y);
    __syncthreads();
#pragma unroll
    for (int k = 0; k < 8; k++) {
        int f = t + 512 * k;
        if (f < FMAX) {
            int g = (NSEQ - f) & (NSEQ - 1);
            float2 zf = make_float2(a[k].x, a[k].y);
            float2 zg = sm[SM_IDX(g)];
            g_Q1[col + f] = make_float2(0.5f * (zf.x + zg.x), 0.5f * (zf.y - zg.y));
            g_K1[col + f] = make_float2(0.5f * (zf.y + zg.y), 0.5f * (zg.x - zf.x));
        }
    }
}

// ---------------- per-frequency circular conv over head_dim (32) -----------
// Only f < FMAX computed; P[N-f] = conj(P[f]) reconstructed in fft_inv.
__global__ void dconv_kernel() {
    __shared__ float Qre[32][65], Qim[32][65], Kre[32][65], Kim[32][65];
    int f0 = blockIdx.x * 64;
    int bh = blockIdx.y;
    size_t base = (size_t)bh * 32 * NSEQ;
    int tid = threadIdx.x;
#pragma unroll
    for (int i = 0; i < 2; i++) {
        int vv = tid + i * 512;
        int d  = vv >> 5;
        int j  = vv & 31;
        const float4* sq = (const float4*)(g_Q1 + base + (size_t)d * NSEQ + f0);
        const float4* sk = (const float4*)(g_K1 + base + (size_t)d * NSEQ + f0);
        float4 x = sq[j];
        Qre[d][2 * j] = x.x; Qim[d][2 * j] = x.y;
        Qre[d][2 * j + 1] = x.z; Qim[d][2 * j + 1] = x.w;
        float4 y = sk[j];
        Kre[d][2 * j] = y.x; Kim[d][2 * j] = y.y;
        Kre[d][2 * j + 1] = y.z; Kim[d][2 * j + 1] = y.w;
    }
    __syncthreads();
    int w = tid >> 5, lane = tid & 31;
#pragma unroll
    for (int rep = 0; rep < 4; rep++) {
        int f = w + rep * 16;
        float qr = Qre[lane][f], qi = Qim[lane][f];
        float kr = Kre[lane][f], ki = Kim[lane][f];
        float ar = 0.f, ai = 0.f;
#pragma unroll
        for (int e = 0; e < 32; e++) {
            float qer = __shfl_sync(0xffffffffu, qr, e);
            float qei = __shfl_sync(0xffffffffu, qi, e);
            int srcl = (lane - e) & 31;
            float ker = __shfl_sync(0xffffffffu, kr, srcl);
            float kei = __shfl_sync(0xffffffffu, ki, srcl);
            ar = fmaf(qer, ker, fmaf(-qei, kei, ar));
            ai = fmaf(qer, kei, fmaf(qei, ker, ai));
        }
        Qre[lane][f] = ar;
        Qim[lane][f] = ai;
    }
    __syncthreads();
#pragma unroll
    for (int i = 0; i < 2; i++) {
        int vv = tid + i * 512;
        int d  = vv >> 5;
        int j  = vv & 31;
        float4* dst = (float4*)(g_P1 + base + (size_t)d * NSEQ + f0);
        float4 x;
        x.x = Qre[d][2 * j];     x.y = Qim[d][2 * j];
        x.z = Qre[d][2 * j + 1]; x.w = Qim[d][2 * j + 1];
        dst[j] = x;
    }
}

// ---------------- inverse seq FFT, packed pair of d-columns ----------------
// P stored only for f <= 2048 (+pad); mirror-conjugate for f > 2048.
__global__ void fft_inv_kernel() {
    __shared__ float2 sm[4608];
    int blk = blockIdx.x;
    int bh = blk >> 4;
    int d0 = (blk & 15) << 1;
    size_t rowa = ((size_t)bh * 32 + d0) * NSEQ;
    size_t rowb = rowa + NSEQ;
    int t = threadIdx.x;
    C a[8];
#pragma unroll
    for (int r = 0; r < 8; r++) {
        int f = t + 512 * r;
        int fs = (f <= 2048) ? f : (NSEQ - f);
        float2 pa = g_P1[rowa + fs];
        float2 pb = g_P1[rowb + fs];
        if (f > 2048) { pa.y = -pa.y; pb.y = -pb.y; }
        a[r] = { pa.x - pb.y, pa.y + pb.x };
    }
    fft_stages<1>(a, sm);
    const float s = 1.0f / (float)NSEQ;
#pragma unroll
    for (int k = 0; k < 8; k++) {
        int n = t + 512 * k;
        g_ATTt[rowa + n] = a[k].x * s;
        g_ATTt[rowb + n] = a[k].y * s;
    }
}

// ---------------- fused epilogue: transpose-in-smem + softmax + LN ---------
// One block per (batch b, 32-token tile). Reads ATTt [b,c,n] coalesced,
// transposes via padded smem tile, then per-token softmax(head) + gate +
// residual + LayerNorm, writing Out token-major coalesced.
__global__ void __launch_bounds__(256)
epilogue_fused_kernel(const float* __restrict__ Vin,
                      const float* __restrict__ gamma,
                      const float* __restrict__ beta,
                      float* __restrict__ Out) {
    __shared__ float tile[256][33];
    __shared__ float p1[8][32], p2[8][32];
    int n0 = blockIdx.x * 32;
    int b  = blockIdx.y;
    int tid = threadIdx.x, wid = tid >> 5, lane = tid & 31;

    // coalesced load: warp-per-channel-row, 32 tokens each (128B lines)
#pragma unroll
    for (int c = wid; c < 256; c += 8)
        tile[c][lane] = g_ATTt[((size_t)b * 256 + c) * NSEQ + n0 + lane];
    __syncthreads();

    // pass 1: softmax over head (warp == head), gate, residual, partial sums
#pragma unroll 4
    for (int j = 0; j < 32; j++) {
        size_t idx = ((size_t)b * NSEQ + n0 + j) * 256 + tid;
        float a = tile[tid][j];
        float m = a;
#pragma unroll
        for (int o = 16; o; o >>= 1) m = fmaxf(m, __shfl_xor_sync(0xffffffffu, m, o));
        float e = __expf(a - m);
        float s = e;
#pragma unroll
        for (int o = 16; o; o >>= 1) s += __shfl_xor_sync(0xffffffffu, s, o);
        float gg = g_VL[idx] * (e / s) + Vin[idx];
        float s1 = gg, s2 = gg * gg;
#pragma unroll
        for (int o = 16; o; o >>= 1) {
            s1 += __shfl_xor_sync(0xffffffffu, s1, o);
            s2 += __shfl_xor_sync(0xffffffffu, s2, o);
        }
        tile[tid][j] = gg;                 // each (tid, j) owned by one thread
        if (lane == 0) { p1[wid][j] = s1; p2[wid][j] = s2; }
    }
    __syncthreads();

    // pass 2: LayerNorm
    float gam = gamma[tid], bet = beta[tid];
#pragma unroll 4
    for (int j = 0; j < 32; j++) {
        float t1 = 0.f, t2 = 0.f;
#pragma unroll
        for (int i = 0; i < 8; i++) { t1 += p1[i][j]; t2 += p2[i][j]; }
        float mu  = t1 * (1.0f / 256.0f);
        float var = t2 * (1.0f / 256.0f) - mu * mu;
        size_t idx = ((size_t)b * NSEQ + n0 + j) * 256 + tid;
        Out[idx] = (tile[tid][j] - mu) * rsqrtf(var + 1e-5f) * gam + bet;
    }
}

// ---------------- launch ----------------------------------------------------
extern "C" void kernel_launch(void* const* d_in, const int* in_sizes, int n_in,
                              void* d_out, int out_size) {
    const float* q     = (const float*)d_in[0];
    const float* k     = (const float*)d_in[1];
    const float* v     = (const float*)d_in[2];
    const float* Wq    = (const float*)d_in[3];
    const float* bq    = (const float*)d_in[4];
    const float* Wk    = (const float*)d_in[5];
    const float* bk    = (const float*)d_in[6];
    const float* Wv    = (const float*)d_in[7];
    const float* bv    = (const float*)d_in[8];
    const float* gamma = (const float*)d_in[9];
    const float* beta  = (const float*)d_in[10];
    float* out = (float*)d_out;

    init_tw_kernel<<<4, 1024>>>();

    proj_mma_kernel<<<dim3(TOK / 128, 2, 3), 256>>>(
        q, k, v, Wq, bq, Wk, bk, Wv, bv);

    fft_fwd_kernel<<<BATCH * 256, 512>>>();

    dconv_kernel<<<dim3(FMAX / 64, BATCH * HEADS), 512>>>();

    fft_inv_kernel<<<BATCH * HEADS * (HD / 2), 512>>>();

    epilogue_fused_kernel<<<dim3(NSEQ / 32, BATCH), 256>>>(v, gamma, beta, out);
}

// round 14
// speedup vs baseline: 2.3725x; 1.0893x over previous
#include <cuda_runtime.h>
#include <cuda_bf16.h>
#include <cstdint>

// Problem constants
#define BATCH 8
#define NSEQ  4096
#define CH    256
#define HEADS 8
#define HD    32
#define TOK   (BATCH * NSEQ)          // 32768 tokens
#define ELEMS (TOK * CH)              // 8,388,608
#define FMAX  2112                    // spectra stored/computed for f < FMAX

// ---------------- scratch (device globals; no allocation allowed) ----------
__device__ float  g_QLt[ELEMS];       // channel-major [b,c,n]
__device__ float  g_KLt[ELEMS];
__device__ float  g_VL [ELEMS];       // token-major [b,n,c]
__device__ float2 g_Q1 [ELEMS];       // seq-spectra, layout [(b*256+c), f], f<FMAX valid
__device__ float2 g_K1 [ELEMS];
__device__ float2 g_P1 [ELEMS];
__device__ float  g_ATTt[ELEMS];      // [b,c,n]
__device__ float2 g_tw [4096];        // exp(-2*pi*i*m/4096)

// ---------------- twiddle init ---------------------------------------------
__global__ void init_tw_kernel() {
    int j = blockIdx.x * blockDim.x + threadIdx.x;
    if (j < 4096) {
        double a = -2.0 * 3.14159265358979323846 * (double)j / 4096.0;
        g_tw[j] = make_float2((float)cos(a), (float)sin(a));
    }
}

// ===================== warp-MMA helpers (sm_80+ baseline PTX) ===============
__device__ __forceinline__ uint32_t smem_u32(const void* p) {
    uint32_t a;
    asm("{ .reg .u64 t; cvta.to.shared.u64 t, %1; cvt.u32.u64 %0, t; }"
        : "=r"(a) : "l"(p));
    return a;
}
__device__ __forceinline__ void ldm_x4(uint32_t addr, uint32_t r[4]) {
    asm volatile("ldmatrix.sync.aligned.m8n8.x4.shared.b16 {%0,%1,%2,%3}, [%4];"
                 : "=r"(r[0]), "=r"(r[1]), "=r"(r[2]), "=r"(r[3]) : "r"(addr));
}
__device__ __forceinline__ void mma16816(float c[4], const uint32_t a[4],
                                         const uint32_t b[2]) {
    asm volatile("mma.sync.aligned.m16n8k16.row.col.f32.bf16.bf16.f32 "
                 "{%0,%1,%2,%3}, {%4,%5,%6,%7}, {%8,%9}, {%0,%1,%2,%3};"
                 : "+f"(c[0]), "+f"(c[1]), "+f"(c[2]), "+f"(c[3])
                 : "r"(a[0]), "r"(a[1]), "r"(a[2]), "r"(a[3]),
                   "r"(b[0]), "r"(b[1]));
}

// ===================== tensor-core projection GEMM ==========================
#define PSTR 40
#define PJ_ARR (128 * PSTR)           // bf16 elements per operand part

__device__ __forceinline__ void split_store(__nv_bfloat16* hb, __nv_bfloat16* lb,
                                            int row, int kl, float4 x) {
    int off = row * PSTR + kl;
    __nv_bfloat16 h0 = __float2bfloat16(x.x);
    __nv_bfloat16 h1 = __float2bfloat16(x.y);
    __nv_bfloat16 h2 = __float2bfloat16(x.z);
    __nv_bfloat16 h3 = __float2bfloat16(x.w);
    uint2 hv;
    hv.x = ((uint32_t)__bfloat16_as_ushort(h1) << 16) | __bfloat16_as_ushort(h0);
    hv.y = ((uint32_t)__bfloat16_as_ushort(h3) << 16) | __bfloat16_as_ushort(h2);
    *(uint2*)(hb + off) = hv;
    __nv_bfloat16 l0 = __float2bfloat16(x.x - __bfloat162float(h0));
    __nv_bfloat16 l1 = __float2bfloat16(x.y - __bfloat162float(h1));
    __nv_bfloat16 l2 = __float2bfloat16(x.z - __bfloat162float(h2));
    __nv_bfloat16 l3 = __float2bfloat16(x.w - __bfloat162float(h3));
    uint2 lv;
    lv.x = ((uint32_t)__bfloat16_as_ushort(l1) << 16) | __bfloat16_as_ushort(l0);
    lv.y = ((uint32_t)__bfloat16_as_ushort(l3) << 16) | __bfloat16_as_ushort(l2);
    *(uint2*)(lb + off) = lv;
}

__global__ void __launch_bounds__(256, 2)
proj_mma_kernel(const float* __restrict__ q, const float* __restrict__ k,
                const float* __restrict__ v,
                const float* __restrict__ Wq, const float* __restrict__ bq,
                const float* __restrict__ Wk, const float* __restrict__ bk,
                const float* __restrict__ Wv, const float* __restrict__ bv) {
    __shared__ __align__(16) union {
        struct {
            __nv_bfloat16 AH[PJ_ARR], AL[PJ_ARR], BH[PJ_ARR], BL[PJ_ARR];
        } op;
        float tr[64 * 132];
    } sm;

    int which = blockIdx.z;
    const float* X    = (which == 0) ? q  : (which == 1) ? k  : v;
    const float* W    = (which == 0) ? Wq : (which == 1) ? Wk : Wv;
    const float* bias = (which == 0) ? bq : (which == 1) ? bk : bv;
    int bm = blockIdx.x * 128;
    int bn = blockIdx.y * 128;
    int tid = threadIdx.x, wid = tid >> 5, lane = tid & 31;
    int wm = wid & 3, wn = wid >> 2;            // 4 warps in M, 2 in N
    int m0 = wm * 32, n0w = wn * 64;
    int g = lane >> 2, t4 = lane & 3;

    uint32_t uAH = smem_u32(sm.op.AH);
    uint32_t uAL = smem_u32(sm.op.AL);
    uint32_t uBH = smem_u32(sm.op.BH);
    uint32_t uBL = smem_u32(sm.op.BL);

    float acc[2][8][4];
#pragma unroll
    for (int mi = 0; mi < 2; mi++)
#pragma unroll
        for (int nj = 0; nj < 8; nj++)
#pragma unroll
            for (int e = 0; e < 4; e++) acc[mi][nj][e] = 0.f;

    int a_row = (lane & 15);
    int a_kh  = (lane >> 4) * 8;
    int b_n   = (lane >> 4) * 8 + (lane & 7);
    int b_kh  = ((lane >> 3) & 1) * 8;

    for (int chunk = 0; chunk < 8; chunk++) {
        int k0 = chunk * 32;
#pragma unroll
        for (int i = 0; i < 4; i++) {
            int idx = tid + i * 256;
            int row = idx >> 3;
            int kl  = (idx & 7) * 4;
            float4 x = *(const float4*)(X + (size_t)(bm + row) * 256 + k0 + kl);
            split_store(sm.op.AH, sm.op.AL, row, kl, x);
            float4 w = *(const float4*)(W + (size_t)(bn + row) * 256 + k0 + kl);
            split_store(sm.op.BH, sm.op.BL, row, kl, w);
        }
        __syncthreads();
#pragma unroll
        for (int ks = 0; ks < 2; ks++) {
            int kk = ks * 16;
            uint32_t ah[2][4], al[2][4], bb[8][2];
#pragma unroll
            for (int mi = 0; mi < 2; mi++) {
                uint32_t off = (uint32_t)((m0 + mi * 16 + a_row) * PSTR + kk + a_kh) * 2;
                ldm_x4(uAH + off, ah[mi]);
                ldm_x4(uAL + off, al[mi]);
            }
#pragma unroll
            for (int nj2 = 0; nj2 < 4; nj2++) {
                uint32_t off = (uint32_t)((n0w + nj2 * 16 + b_n) * PSTR + kk + b_kh) * 2;
                uint32_t r[4];
                ldm_x4(uBH + off, r);
                bb[2 * nj2][0] = r[0]; bb[2 * nj2][1] = r[1];
                bb[2 * nj2 + 1][0] = r[2]; bb[2 * nj2 + 1][1] = r[3];
            }
#pragma unroll
            for (int mi = 0; mi < 2; mi++)
#pragma unroll
                for (int nj = 0; nj < 8; nj++) mma16816(acc[mi][nj], ah[mi], bb[nj]);
#pragma unroll
            for (int mi = 0; mi < 2; mi++)
#pragma unroll
                for (int nj = 0; nj < 8; nj++) mma16816(acc[mi][nj], al[mi], bb[nj]);
#pragma unroll
            for (int nj2 = 0; nj2 < 4; nj2++) {
                uint32_t off = (uint32_t)((n0w + nj2 * 16 + b_n) * PSTR + kk + b_kh) * 2;
                uint32_t r[4];
                ldm_x4(uBL + off, r);
                bb[2 * nj2][0] = r[0]; bb[2 * nj2][1] = r[1];
                bb[2 * nj2 + 1][0] = r[2]; bb[2 * nj2 + 1][1] = r[3];
            }
#pragma unroll
            for (int mi = 0; mi < 2; mi++)
#pragma unroll
                for (int nj = 0; nj < 8; nj++) mma16816(acc[mi][nj], ah[mi], bb[nj]);
        }
        __syncthreads();
    }

    if (which == 2) {
#pragma unroll
        for (int mi = 0; mi < 2; mi++)
#pragma unroll
            for (int eh = 0; eh < 2; eh++) {
                int m = bm + m0 + mi * 16 + g + eh * 8;
#pragma unroll
                for (int nj = 0; nj < 8; nj++) {
                    int col = n0w + nj * 8 + 2 * t4;
                    float2 o;
                    o.x = acc[mi][nj][eh * 2 + 0] + bias[bn + col];
                    o.y = acc[mi][nj][eh * 2 + 1] + bias[bn + col + 1];
                    *(float2*)(g_VL + (size_t)m * 256 + bn + col) = o;
                }
            }
        return;
    }
    float* Out = (which == 0) ? g_QLt : g_KLt;
    int b  = bm >> 12;
    int n0 = bm & 4095;
    for (int p = 0; p < 2; p++) {
        __syncthreads();
        if (wn == p) {
#pragma unroll
            for (int mi = 0; mi < 2; mi++)
#pragma unroll
                for (int eh = 0; eh < 2; eh++) {
                    int ml = m0 + mi * 16 + g + eh * 8;
#pragma unroll
                    for (int nj = 0; nj < 8; nj++) {
                        int cl = nj * 8 + 2 * t4;
                        sm.tr[(size_t)cl * 132 + ml] =
                            acc[mi][nj][eh * 2 + 0] + bias[bn + n0w + cl];
                        sm.tr[(size_t)(cl + 1) * 132 + ml] =
                            acc[mi][nj][eh * 2 + 1] + bias[bn + n0w + cl + 1];
                    }
                }
        }
        __syncthreads();
        int cl  = tid >> 2;
        int qtr = tid & 3;
        float* dst = Out + ((size_t)(b * 256 + bn + p * 64 + cl)) * NSEQ + n0 + qtr * 32;
        const float* src = sm.tr + (size_t)cl * 132 + qtr * 32;
#pragma unroll
        for (int j = 0; j < 8; j++) {
            float4 o;
            o.x = src[4 * j + 0]; o.y = src[4 * j + 1];
            o.z = src[4 * j + 2]; o.w = src[4 * j + 3];
            *(float4*)(dst + 4 * j) = o;
        }
    }
}

// ---------------- complex helpers ------------------------------------------
struct C { float x, y; };
__device__ __forceinline__ C cadd(C a, C b) { return {a.x + b.x, a.y + b.y}; }
__device__ __forceinline__ C csub(C a, C b) { return {a.x - b.x, a.y - b.y}; }
__device__ __forceinline__ C cmul(C a, C b) {
    return {a.x * b.x - a.y * b.y, a.x * b.y + a.y * b.x};
}
template <int INV> __device__ __forceinline__ C crot(C a) {
    return INV ? C{-a.y, a.x} : C{a.y, -a.x};
}
template <int INV> __device__ __forceinline__ C tw(int m) {
    float2 w = g_tw[m];
    return INV ? C{w.x, -w.y} : C{w.x, w.y};
}

// ---------------- in-register 8-point DFT ----------------------------------
template <int INV>
__device__ __forceinline__ void dft8(C a[8]) {
    const float S = 0.70710678118654752440f;
    C t0 = cadd(a[0], a[4]), t1 = csub(a[0], a[4]);
    C t2 = cadd(a[2], a[6]), t3 = csub(a[2], a[6]);
    C E0 = cadd(t0, t2), E2 = csub(t0, t2);
    C E1 = cadd(t1, crot<INV>(t3)), E3 = csub(t1, crot<INV>(t3));
    C u0 = cadd(a[1], a[5]), u1 = csub(a[1], a[5]);
    C u2 = cadd(a[3], a[7]), u3 = csub(a[3], a[7]);
    C O0 = cadd(u0, u2), O2 = csub(u0, u2);
    C O1 = cadd(u1, crot<INV>(u3)), O3 = csub(u1, crot<INV>(u3));
    C w1 = INV ? C{S, S} : C{S, -S};
    C w3 = INV ? C{-S, S} : C{-S, -S};
    C o1 = cmul(w1, O1);
    C o2 = crot<INV>(O2);
    C o3 = cmul(w3, O3);
    a[0] = cadd(E0, O0); a[4] = csub(E0, O0);
    a[1] = cadd(E1, o1); a[5] = csub(E1, o1);
    a[2] = cadd(E2, o2); a[6] = csub(E2, o2);
    a[3] = cadd(E3, o3); a[7] = csub(E3, o3);
}

// ---------------- Stockham radix-8 4096-pt FFT core ------------------------
#define SM_IDX(i) ((i) + ((i) >> 3))

template <int INV>
__device__ __forceinline__ void fft_stages(C a[8], float2* sm) {
    const int t = threadIdx.x;
    dft8<INV>(a);
#pragma unroll
    for (int k = 1; k < 8; k++) a[k] = cmul(a[k], tw<INV>(t * k));
#pragma unroll
    for (int k = 0; k < 8; k++) { C v = a[k]; sm[SM_IDX(8 * t + k)] = make_float2(v.x, v.y); }
    __syncthreads();
    {
#pragma unroll
        for (int r = 0; r < 8; r++) { float2 v = sm[SM_IDX(t + 512 * r)]; a[r] = {v.x, v.y}; }
        __syncthreads();
        dft8<INV>(a);
        int p = t >> 3, qq = t & 7;
#pragma unroll
        for (int k = 1; k < 8; k++) a[k] = cmul(a[k], tw<INV>(8 * p * k));
#pragma unroll
        for (int k = 0; k < 8; k++) { C v = a[k]; sm[SM_IDX(qq + 64 * p + 8 * k)] = make_float2(v.x, v.y); }
        __syncthreads();
    }
    {
#pragma unroll
        for (int r = 0; r < 8; r++) { float2 v = sm[SM_IDX(t + 512 * r)]; a[r] = {v.x, v.y}; }
        __syncthreads();
        dft8<INV>(a);
        int p = t >> 6, qq = t & 63;
#pragma unroll
        for (int k = 1; k < 8; k++) a[k] = cmul(a[k], tw<INV>(64 * p * k));
#pragma unroll
        for (int k = 0; k < 8; k++) { C v = a[k]; sm[SM_IDX(qq + 512 * p + 64 * k)] = make_float2(v.x, v.y); }
        __syncthreads();
    }
#pragma unroll
    for (int r = 0; r < 8; r++) { float2 v = sm[SM_IDX(t + 512 * r)]; a[r] = {v.x, v.y}; }
    dft8<INV>(a);
}

// ---------------- forward seq FFT, packed z = ql + i*kl --------------------
__global__ void fft_fwd_kernel() {
    __shared__ float2 sm[4608];
    int blk = blockIdx.x;
    size_t col = (size_t)blk * NSEQ;
    int t = threadIdx.x;
    C a[8];
#pragma unroll
    for (int r = 0; r < 8; r++) {
        int n = t + 512 * r;
        a[r] = { g_QLt[col + n], g_KLt[col + n] };
    }
    fft_stages<0>(a, sm);
    __syncthreads();
#pragma unroll
    for (int k = 0; k < 8; k++) sm[SM_IDX(t + 512 * k)] = make_float2(a[k].x, a[k].y);
    __syncthreads();
#pragma unroll
    for (int k = 0; k < 8; k++) {
        int f = t + 512 * k;
        if (f < FMAX) {
            int g = (NSEQ - f) & (NSEQ - 1);
            float2 zf = make_float2(a[k].x, a[k].y);
            float2 zg = sm[SM_IDX(g)];
            g_Q1[col + f] = make_float2(0.5f * (zf.x + zg.x), 0.5f * (zf.y - zg.y));
            g_K1[col + f] = make_float2(0.5f * (zf.y + zg.y), 0.5f * (zg.x - zf.x));
        }
    }
}

// ---------------- per-frequency circular conv over head_dim (32) -----------
// Conv theorem over d: P = IDFT32(DFT32(Q) * DFT32(K)) per (bh, f).
// lane = d; forward = radix-2 DIF via shfl_xor (natural in -> bit-reversed out),
// pointwise cmul in BR order (consistent for Q,K), inverse = DIT (BR in ->
// natural out). The 1/32 IDFT scale is folded into fft_inv's scale.
__device__ __forceinline__ void bfly_fwd(float2& z, int s, float2 w, int lane) {
    float tx = __shfl_xor_sync(0xffffffffu, z.x, s);
    float ty = __shfl_xor_sync(0xffffffffu, z.y, s);
    if (lane & s) {
        float ux = tx - z.x, uy = ty - z.y;
        z.x = ux * w.x - uy * w.y;
        z.y = ux * w.y + uy * w.x;
    } else {
        z.x += tx; z.y += ty;
    }
}
__device__ __forceinline__ void bfly_inv(float2& z, int s, float2 wc, int lane) {
    float tx, ty;
    if (lane & s) {
        tx = z.x * wc.x - z.y * wc.y;
        ty = z.x * wc.y + z.y * wc.x;
    } else { tx = z.x; ty = z.y; }
    float px = __shfl_xor_sync(0xffffffffu, tx, s);
    float py = __shfl_xor_sync(0xffffffffu, ty, s);
    if (lane & s) { z.x = px - tx; z.y = py - ty; }
    else          { z.x = tx + px; z.y = ty + py; }
}

__global__ void dconv_kernel() {
    __shared__ float Qre[32][65], Qim[32][65], Kre[32][65], Kim[32][65];
    int f0 = blockIdx.x * 64;
    int bh = blockIdx.y;
    size_t base = (size_t)bh * 32 * NSEQ;
    int tid = threadIdx.x;
#pragma unroll
    for (int i = 0; i < 2; i++) {
        int vv = tid + i * 512;
        int d  = vv >> 5;
        int j  = vv & 31;
        const float4* sq = (const float4*)(g_Q1 + base + (size_t)d * NSEQ + f0);
        const float4* sk = (const float4*)(g_K1 + base + (size_t)d * NSEQ + f0);
        float4 x = sq[j];
        Qre[d][2 * j] = x.x; Qim[d][2 * j] = x.y;
        Qre[d][2 * j + 1] = x.z; Qim[d][2 * j + 1] = x.w;
        float4 y = sk[j];
        Kre[d][2 * j] = y.x; Kim[d][2 * j] = y.y;
        Kre[d][2 * j + 1] = y.z; Kim[d][2 * j + 1] = y.w;
    }
    __syncthreads();
    int w = tid >> 5, lane = tid & 31;
    // per-lane twiddles: W32^m = g_tw[m*128] (forward); conj for inverse
    float2 w16 = g_tw[(lane & 15) * 128];
    float2 w8  = g_tw[(lane & 7)  * 256];
    float2 w4  = g_tw[(lane & 3)  * 512];
    float2 w2  = g_tw[(lane & 1)  * 1024];
    const float2 w1 = make_float2(1.f, 0.f);
    float2 c16 = make_float2(w16.x, -w16.y);
    float2 c8  = make_float2(w8.x,  -w8.y);
    float2 c4  = make_float2(w4.x,  -w4.y);
    float2 c2  = make_float2(w2.x,  -w2.y);
#pragma unroll
    for (int rep = 0; rep < 4; rep++) {
        int f = w + rep * 16;
        float2 qz = make_float2(Qre[lane][f], Qim[lane][f]);
        float2 kz = make_float2(Kre[lane][f], Kim[lane][f]);
        // forward DIF (natural -> bit-reversed)
        bfly_fwd(qz, 16, w16, lane); bfly_fwd(kz, 16, w16, lane);
        bfly_fwd(qz,  8, w8,  lane); bfly_fwd(kz,  8, w8,  lane);
        bfly_fwd(qz,  4, w4,  lane); bfly_fwd(kz,  4, w4,  lane);
        bfly_fwd(qz,  2, w2,  lane); bfly_fwd(kz,  2, w2,  lane);
        bfly_fwd(qz,  1, w1,  lane); bfly_fwd(kz,  1, w1,  lane);
        // pointwise product (both in same BR order)
        float2 pz;
        pz.x = qz.x * kz.x - qz.y * kz.y;
        pz.y = qz.x * kz.y + qz.y * kz.x;
        // inverse DIT (bit-reversed -> natural); 1/32 folded into fft_inv
        bfly_inv(pz,  1, w1,  lane);
        bfly_inv(pz,  2, c2,  lane);
        bfly_inv(pz,  4, c4,  lane);
        bfly_inv(pz,  8, c8,  lane);
        bfly_inv(pz, 16, c16, lane);
        Qre[lane][f] = pz.x;
        Qim[lane][f] = pz.y;
    }
    __syncthreads();
#pragma unroll
    for (int i = 0; i < 2; i++) {
        int vv = tid + i * 512;
        int d  = vv >> 5;
        int j  = vv & 31;
        float4* dst = (float4*)(g_P1 + base + (size_t)d * NSEQ + f0);
        float4 x;
        x.x = Qre[d][2 * j];     x.y = Qim[d][2 * j];
        x.z = Qre[d][2 * j + 1]; x.w = Qim[d][2 * j + 1];
        dst[j] = x;
    }
}

// ---------------- inverse seq FFT, packed pair of d-columns ----------------
// P stored only for f <= 2048 (+pad); mirror-conjugate for f > 2048.
// Scale = 1/(4096*32): seq IFFT normalization plus folded d-IDFT 1/32.
__global__ void fft_inv_kernel() {
    __shared__ float2 sm[4608];
    int blk = blockIdx.x;
    int bh = blk >> 4;
    int d0 = (blk & 15) << 1;
    size_t rowa = ((size_t)bh * 32 + d0) * NSEQ;
    size_t rowb = rowa + NSEQ;
    int t = threadIdx.x;
    C a[8];
#pragma unroll
    for (int r = 0; r < 8; r++) {
        int f = t + 512 * r;
        int fs = (f <= 2048) ? f : (NSEQ - f);
        float2 pa = g_P1[rowa + fs];
        float2 pb = g_P1[rowb + fs];
        if (f > 2048) { pa.y = -pa.y; pb.y = -pb.y; }
        a[r] = { pa.x - pb.y, pa.y + pb.x };
    }
    fft_stages<1>(a, sm);
    const float s = 1.0f / (float)(NSEQ * 32);
#pragma unroll
    for (int k = 0; k < 8; k++) {
        int n = t + 512 * k;
        g_ATTt[rowa + n] = a[k].x * s;
        g_ATTt[rowb + n] = a[k].y * s;
    }
}

// ---------------- fused epilogue: transpose-in-smem + softmax + LN ---------
__global__ void __launch_bounds__(256)
epilogue_fused_kernel(const float* __restrict__ Vin,
                      const float* __restrict__ gamma,
                      const float* __restrict__ beta,
                      float* __restrict__ Out) {
    __shared__ float tile[256][33];
    __shared__ float p1[8][32], p2[8][32];
    int n0 = blockIdx.x * 32;
    int b  = blockIdx.y;
    int tid = threadIdx.x, wid = tid >> 5, lane = tid & 31;

#pragma unroll
    for (int c = wid; c < 256; c += 8)
        tile[c][lane] = g_ATTt[((size_t)b * 256 + c) * NSEQ + n0 + lane];
    __syncthreads();

#pragma unroll 4
    for (int j = 0; j < 32; j++) {
        size_t idx = ((size_t)b * NSEQ + n0 + j) * 256 + tid;
        float a = tile[tid][j];
        float m = a;
#pragma unroll
        for (int o = 16; o; o >>= 1) m = fmaxf(m, __shfl_xor_sync(0xffffffffu, m, o));
        float e = __expf(a - m);
        float s = e;
#pragma unroll
        for (int o = 16; o; o >>= 1) s += __shfl_xor_sync(0xffffffffu, s, o);
        float gg = g_VL[idx] * (e / s) + Vin[idx];
        float s1 = gg, s2 = gg * gg;
#pragma unroll
        for (int o = 16; o; o >>= 1) {
            s1 += __shfl_xor_sync(0xffffffffu, s1, o);
            s2 += __shfl_xor_sync(0xffffffffu, s2, o);
        }
        tile[tid][j] = gg;
        if (lane == 0) { p1[wid][j] = s1; p2[wid][j] = s2; }
    }
    __syncthreads();

    float gam = gamma[tid], bet = beta[tid];
#pragma unroll 4
    for (int j = 0; j < 32; j++) {
        float t1 = 0.f, t2 = 0.f;
#pragma unroll
        for (int i = 0; i < 8; i++) { t1 += p1[i][j]; t2 += p2[i][j]; }
        float mu  = t1 * (1.0f / 256.0f);
        float var = t2 * (1.0f / 256.0f) - mu * mu;
        size_t idx = ((size_t)b * NSEQ + n0 + j) * 256 + tid;
        Out[idx] = (tile[tid][j] - mu) * rsqrtf(var + 1e-5f) * gam + bet;
    }
}

// ---------------- launch ----------------------------------------------------
extern "C" void kernel_launch(void* const* d_in, const int* in_sizes, int n_in,
                              void* d_out, int out_size) {
    const float* q     = (const float*)d_in[0];
    const float* k     = (const float*)d_in[1];
    const float* v     = (const float*)d_in[2];
    const float* Wq    = (const float*)d_in[3];
    const float* bq    = (const float*)d_in[4];
    const float* Wk    = (const float*)d_in[5];
    const float* bk    = (const float*)d_in[6];
    const float* Wv    = (const float*)d_in[7];
    const float* bv    = (const float*)d_in[8];
    const float* gamma = (const float*)d_in[9];
    const float* beta  = (const float*)d_in[10];
    float* out = (float*)d_out;

    init_tw_kernel<<<4, 1024>>>();

    proj_mma_kernel<<<dim3(TOK / 128, 2, 3), 256>>>(
        q, k, v, Wq, bq, Wk, bk, Wv, bv);

    fft_fwd_kernel<<<BATCH * 256, 512>>>();

    dconv_kernel<<<dim3(FMAX / 64, BATCH * HEADS), 512>>>();

    fft_inv_kernel<<<BATCH * HEADS * (HD / 2), 512>>>();

    epilogue_fused_kernel<<<dim3(NSEQ / 32, BATCH), 256>>>(v, gamma, beta, out);
}